// round 11
// baseline (speedup 1.0000x reference)
#include <cuda_runtime.h>
#include <cuda_bf16.h>
#include <cstdint>

#define N_H_NODES 50000
#define N_G_NODES 50000
#define N_GC 128
#define N_EDGES_MAX 1600000

// Static device scratch (no allocs allowed).
__device__ __align__(128) float g_accum[(size_t)N_G_NODES * N_GC];   // 25.6 MB
__device__ int g_cnt[N_G_NODES];        // histogram -> cursor array
__device__ int g_perm[N_EDGES_MAX];     // tgt-sorted edge order

__device__ __forceinline__ float lrelu(float v) { return v >= 0.0f ? v : 0.1f * v; }

// ---------------------------------------------------------------------------
// mma.sync / ldmatrix helpers (baseline PTX, compiles for compute_103)
// ---------------------------------------------------------------------------
__device__ __forceinline__ uint32_t smem_to_u32(const void* p) {
    uint32_t a;
    asm("{ .reg .u64 t; cvta.to.shared.u64 t, %1; cvt.u32.u64 %0, t; }" : "=r"(a) : "l"(p));
    return a;
}

__device__ __forceinline__ void ldsm4(uint32_t a[4], uint32_t addr) {
    asm volatile("ldmatrix.sync.aligned.m8n8.x4.shared.b16 {%0,%1,%2,%3}, [%4];"
                 : "=r"(a[0]), "=r"(a[1]), "=r"(a[2]), "=r"(a[3]) : "r"(addr));
}
__device__ __forceinline__ void ldsm4t(uint32_t b[4], uint32_t addr) {
    asm volatile("ldmatrix.sync.aligned.m8n8.x4.trans.shared.b16 {%0,%1,%2,%3}, [%4];"
                 : "=r"(b[0]), "=r"(b[1]), "=r"(b[2]), "=r"(b[3]) : "r"(addr));
}
__device__ __forceinline__ void mma16816(float d[4], const uint32_t a[4], const uint32_t b[2]) {
    asm volatile("mma.sync.aligned.m16n8k16.row.col.f32.bf16.bf16.f32 "
                 "{%0,%1,%2,%3}, {%4,%5,%6,%7}, {%8,%9}, {%0,%1,%2,%3};"
                 : "+f"(d[0]), "+f"(d[1]), "+f"(d[2]), "+f"(d[3])
                 : "r"(a[0]), "r"(a[1]), "r"(a[2]), "r"(a[3]), "r"(b[0]), "r"(b[1]));
}

__device__ __forceinline__ void bf16_split(float v, uint16_t& h, uint16_t& l) {
    __nv_bfloat16 hb = __float2bfloat16_rn(v);
    h = __bfloat16_as_ushort(hb);
    l = __bfloat16_as_ushort(__float2bfloat16_rn(v - __bfloat162float(hb)));
}

__device__ __forceinline__ void red_add_v4(float* p, float a, float b, float c, float d) {
    asm volatile("red.global.add.v4.f32 [%0], {%1, %2, %3, %4};"
                 :: "l"(p), "f"(a), "f"(b), "f"(c), "f"(d) : "memory");
}

// ---------------------------------------------------------------------------
// Counting-sort pipeline (runs every launch; graph-capturable)
// ---------------------------------------------------------------------------
__global__ void zero_accum_kernel() {
    size_t n4 = (size_t)N_G_NODES * N_GC / 4;
    float4 z = make_float4(0.f, 0.f, 0.f, 0.f);
    float4* p = reinterpret_cast<float4*>(g_accum);
    for (size_t i = (size_t)blockIdx.x * blockDim.x + threadIdx.x; i < n4;
         i += (size_t)gridDim.x * blockDim.x)
        p[i] = z;
    for (int i = blockIdx.x * blockDim.x + threadIdx.x; i < N_G_NODES;
         i += gridDim.x * blockDim.x)
        g_cnt[i] = 0;
}

__global__ void hist_kernel(const int* __restrict__ eidx, int E) {
    const int* tgtp = eidx + E;
    for (int e = blockIdx.x * blockDim.x + threadIdx.x; e < E;
         e += gridDim.x * blockDim.x) {
        int t = tgtp[e];
        if (t < 0) t = 0;
        if (t >= N_G_NODES) t = N_G_NODES - 1;
        atomicAdd(&g_cnt[t], 1);
    }
}

// Single-block exclusive scan over g_cnt; rewrites g_cnt in place with
// starting offsets (cursor array for the rank-scatter).
__global__ void scan_kernel() {
    __shared__ int wsum[32];
    const int tid = threadIdx.x;
    const int lane = tid & 31, wid = tid >> 5;
    const int chunk = (N_G_NODES + 1023) / 1024;
    const int base = tid * chunk;

    int s = 0;
    for (int j = 0; j < chunk; ++j) {
        int i = base + j;
        if (i < N_G_NODES) s += g_cnt[i];
    }
    int v = s;
    for (int d = 1; d < 32; d <<= 1) {
        int n = __shfl_up_sync(0xFFFFFFFFu, v, d);
        if (lane >= d) v += n;
    }
    if (lane == 31) wsum[wid] = v;
    __syncthreads();
    if (wid == 0) {
        int w = wsum[lane];
        for (int d = 1; d < 32; d <<= 1) {
            int n = __shfl_up_sync(0xFFFFFFFFu, w, d);
            if (lane >= d) w += n;
        }
        wsum[lane] = w;
    }
    __syncthreads();
    int excl = v - s + (wid > 0 ? wsum[wid - 1] : 0);

    int running = excl;
    for (int j = 0; j < chunk; ++j) {
        int i = base + j;
        if (i < N_G_NODES) {
            int c = g_cnt[i];
            g_cnt[i] = running;
            running += c;
        }
    }
}

__global__ void rank_scatter_kernel(const int* __restrict__ eidx, int E) {
    const int* tgtp = eidx + E;
    for (int e = blockIdx.x * blockDim.x + threadIdx.x; e < E;
         e += gridDim.x * blockDim.x) {
        int t = tgtp[e];
        if (t < 0) t = 0;
        if (t >= N_G_NODES) t = N_G_NODES - 1;
        int r = atomicAdd(&g_cnt[t], 1);
        if (r < N_EDGES_MAX) g_perm[r] = e;
    }
}

// ---------------------------------------------------------------------------
// Fused edge MLP (persistent), bf16x3, warp tile m16 x n128, SORTED order.
// Per 128-edge tile (edges tgt-sorted via g_perm):
//   gather V -> bf16 hi/lo planes; GEMM1 (3-term); register epilogue repack;
//   GEMM2 (3-term); stage O in SMEM; SEGMENTED reduce rows sharing tgt;
//   one red.v4 row-set per distinct tgt in tile (~4-8 instead of 128).
// ---------------------------------------------------------------------------
#define ETH   256
#define PADK  136
#define PLANE (128 * PADK * 2)
#define OPAD  132

#define SO_WAHI 0
#define SO_WALO (SO_WAHI + PLANE)
#define SO_WBHI (SO_WALO + PLANE)
#define SO_WBLO (SO_WBHI + PLANE)
#define SO_VHI  (SO_WBLO + PLANE)          // reused as O staging
#define SO_VLO  (SO_VHI + PLANE)
#define SO_B1A  (SO_VLO + PLANE)
#define SO_B1B  (SO_B1A + 512)
#define SO_SRC  (SO_B1B + 512)
#define SO_TGT  (SO_SRC + 512)
#define SO_PE   (SO_TGT + 512)             // permuted edge ids
#define E_SMEM_BYTES (SO_PE + 512)

__global__ void __launch_bounds__(ETH, 1)
edge_kernel(const float* __restrict__ x_h,
            const float* __restrict__ edge_attr,
            const float* __restrict__ W1a, const float* __restrict__ b1a,
            const float* __restrict__ W1b, const float* __restrict__ b1b,
            const int* __restrict__ eidx, int E)
{
    extern __shared__ char smc[];
    const uint32_t sb = smem_to_u32(smc);
    uint16_t* WaHi = reinterpret_cast<uint16_t*>(smc + SO_WAHI);
    uint16_t* WaLo = reinterpret_cast<uint16_t*>(smc + SO_WALO);
    uint16_t* WbHi = reinterpret_cast<uint16_t*>(smc + SO_WBHI);
    uint16_t* WbLo = reinterpret_cast<uint16_t*>(smc + SO_WBLO);
    uint32_t* Vhi32 = reinterpret_cast<uint32_t*>(smc + SO_VHI);
    uint32_t* Vlo32 = reinterpret_cast<uint32_t*>(smc + SO_VLO);
    float* Ost  = reinterpret_cast<float*>(smc + SO_VHI);
    float* sb1a = reinterpret_cast<float*>(smc + SO_B1A);
    float* sb1b = reinterpret_cast<float*>(smc + SO_B1B);
    int*   s_src = reinterpret_cast<int*>(smc + SO_SRC);
    int*   s_tgt = reinterpret_cast<int*>(smc + SO_TGT);
    int*   s_pe  = reinterpret_cast<int*>(smc + SO_PE);

    const int tid  = threadIdx.x;
    const int wid  = tid >> 5;
    const int lane = tid & 31;

    for (int t = tid; t < 128 * 128; t += ETH) {
        int n = t >> 7, k = t & 127;
        uint16_t h, l;
        bf16_split(W1a[t], h, l);
        WaHi[k * PADK + n] = h; WaLo[k * PADK + n] = l;
        bf16_split(W1b[t], h, l);
        WbHi[k * PADK + n] = h; WbLo[k * PADK + n] = l;
    }
    if (tid < 128) { sb1a[tid] = b1a[tid]; sb1b[tid] = b1b[tid]; }

    const int m0 = wid * 16;
    const int qr = lane >> 2;
    const int qt = lane & 3;

    const uint32_t aoff = (uint32_t)(lane & 15) * (PADK * 2) + (uint32_t)(lane >> 4) * 16;
    const uint32_t boff = ((uint32_t)(lane & 15) * PADK + (uint32_t)(lane >> 4) * 8) * 2;

    const uint32_t vhiA = sb + SO_VHI, vloA = sb + SO_VLO;
    const uint32_t wahiA = sb + SO_WAHI, waloA = sb + SO_WALO;
    const uint32_t wbhiA = sb + SO_WBHI, wbloA = sb + SO_WBLO;

    const int* srcp = eidx;
    const int* tgtp = eidx + E;
    const int numTiles = (E + 127) >> 7;

    for (int tile = blockIdx.x; tile < numTiles; tile += gridDim.x) {
        const int e0 = tile * 128;
        __syncthreads();

        if (tid < 128) {
            int e = e0 + tid;
            int p = 0, s = 0, t = -1;
            if (e < E) {
                p = g_perm[e];
                if (p < 0) p = 0;
                if (p >= E) p = E - 1;
                s = srcp[p];
                t = tgtp[p];
                if (s < 0) s = 0;
                if (s >= N_H_NODES) s = N_H_NODES - 1;
                if (t < 0 || t >= N_G_NODES) t = -1;
            }
            s_src[tid] = s;
            s_tgt[tid] = t;
            s_pe[tid]  = p;
        }
        __syncthreads();

        // Gather + split into V planes. 2 threads per row, 64 cols each.
        {
            const int r = tid >> 1;
            const int half = tid & 1;
            const float4* rp = (half == 0)
                ? reinterpret_cast<const float4*>(x_h + (size_t)s_src[r] * 64)
                : reinterpret_cast<const float4*>(edge_attr + (size_t)s_pe[r] * 64);
            const int base = (r * PADK + half * 64) >> 1;
            #pragma unroll
            for (int q = 0; q < 16; ++q) {
                float4 v = rp[q];
                uint16_t h0, l0, h1, l1;
                bf16_split(v.x, h0, l0); bf16_split(v.y, h1, l1);
                Vhi32[base + 2 * q]     = (uint32_t)h0 | ((uint32_t)h1 << 16);
                Vlo32[base + 2 * q]     = (uint32_t)l0 | ((uint32_t)l1 << 16);
                bf16_split(v.z, h0, l0); bf16_split(v.w, h1, l1);
                Vhi32[base + 2 * q + 1] = (uint32_t)h0 | ((uint32_t)h1 << 16);
                Vlo32[base + 2 * q + 1] = (uint32_t)l0 | ((uint32_t)l1 << 16);
            }
        }
        __syncthreads();

        // --- GEMM 1 ---
        float acc[16][4];
        #pragma unroll
        for (int j = 0; j < 16; ++j)
            #pragma unroll
            for (int q = 0; q < 4; ++q) acc[j][q] = 0.f;

        #pragma unroll
        for (int ks = 0; ks < 8; ++ks) {
            uint32_t ahi[4], alo[4];
            const uint32_t ab = (uint32_t)(m0 * PADK + ks * 16) * 2 + aoff;
            ldsm4(ahi, vhiA + ab);
            ldsm4(alo, vloA + ab);
            #pragma unroll
            for (int np = 0; np < 8; ++np) {
                uint32_t bh[4], bl[4];
                const uint32_t bb = (uint32_t)(ks * 16 * PADK + np * 16) * 2 + boff;
                ldsm4t(bh, wahiA + bb);
                ldsm4t(bl, waloA + bb);
                mma16816(acc[2 * np + 0], ahi, bh + 0);
                mma16816(acc[2 * np + 0], alo, bh + 0);
                mma16816(acc[2 * np + 0], ahi, bl + 0);
                mma16816(acc[2 * np + 1], ahi, bh + 2);
                mma16816(acc[2 * np + 1], alo, bh + 2);
                mma16816(acc[2 * np + 1], ahi, bl + 2);
            }
        }

        // Register epilogue: H = lrelu(acc+b1a) repacked as GEMM2 A-fragments
        uint32_t ah2[8][4], al2[8][4];
        #pragma unroll
        for (int j = 0; j < 16; ++j) {
            const int c = 8 * j + 2 * qt;
            const float bx = sb1a[c], by = sb1a[c + 1];
            uint16_t h0, l0, h1, l1, h2, l2, h3, l3;
            bf16_split(lrelu(acc[j][0] + bx), h0, l0);
            bf16_split(lrelu(acc[j][1] + by), h1, l1);
            bf16_split(lrelu(acc[j][2] + bx), h2, l2);
            bf16_split(lrelu(acc[j][3] + by), h3, l3);
            const int ks2 = j >> 1;
            const int ix = (j & 1) * 2;
            ah2[ks2][ix + 0] = (uint32_t)h0 | ((uint32_t)h1 << 16);
            ah2[ks2][ix + 1] = (uint32_t)h2 | ((uint32_t)h3 << 16);
            al2[ks2][ix + 0] = (uint32_t)l0 | ((uint32_t)l1 << 16);
            al2[ks2][ix + 1] = (uint32_t)l2 | ((uint32_t)l3 << 16);
        }

        // --- GEMM 2 ---
        #pragma unroll
        for (int j = 0; j < 16; ++j)
            #pragma unroll
            for (int q = 0; q < 4; ++q) acc[j][q] = 0.f;

        #pragma unroll
        for (int ks = 0; ks < 8; ++ks) {
            #pragma unroll
            for (int np = 0; np < 8; ++np) {
                uint32_t bh[4], bl[4];
                const uint32_t bb = (uint32_t)(ks * 16 * PADK + np * 16) * 2 + boff;
                ldsm4t(bh, wbhiA + bb);
                ldsm4t(bl, wbloA + bb);
                mma16816(acc[2 * np + 0], ah2[ks], bh + 0);
                mma16816(acc[2 * np + 0], al2[ks], bh + 0);
                mma16816(acc[2 * np + 0], ah2[ks], bl + 0);
                mma16816(acc[2 * np + 1], ah2[ks], bh + 2);
                mma16816(acc[2 * np + 1], al2[ks], bh + 2);
                mma16816(acc[2 * np + 1], ah2[ks], bl + 2);
            }
        }
        __syncthreads();   // V planes dead -> reuse as O staging

        {
            const int r = m0 + qr;
            #pragma unroll
            for (int j = 0; j < 16; ++j) {
                const int c = 8 * j + 2 * qt;
                const float bx = sb1b[c], by = sb1b[c + 1];
                float2* p0 = reinterpret_cast<float2*>(Ost + r * OPAD + c);
                float2* p1 = reinterpret_cast<float2*>(Ost + (r + 8) * OPAD + c);
                *p0 = make_float2(acc[j][0] + bx, acc[j][1] + by);
                *p1 = make_float2(acc[j][2] + bx, acc[j][3] + by);
            }
        }
        __syncthreads();

        // Segmented scatter: rows are tgt-sorted; heads accumulate their run
        // and issue ONE red.v4 row-set per distinct target.
        {
            const int r = tid >> 1;
            const int h = tid & 1;
            const int t = s_tgt[r];
            const bool head = (t >= 0) && (r == 0 || s_tgt[r - 1] != t);
            if (head) {
                int rend = r + 1;
                while (rend < 128 && s_tgt[rend] == t) ++rend;
                float* gp = g_accum + (size_t)t * 128 + h * 64;
                #pragma unroll
                for (int qb = 0; qb < 16; qb += 8) {
                    float4 s[8];
                    const float4* op = reinterpret_cast<const float4*>(
                        Ost + r * OPAD + h * 64) + qb;
                    #pragma unroll
                    for (int q = 0; q < 8; ++q) s[q] = op[q];
                    for (int rr = r + 1; rr < rend; ++rr) {
                        const float4* o2 = reinterpret_cast<const float4*>(
                            Ost + rr * OPAD + h * 64) + qb;
                        #pragma unroll
                        for (int q = 0; q < 8; ++q) {
                            float4 v = o2[q];
                            s[q].x += v.x; s[q].y += v.y;
                            s[q].z += v.z; s[q].w += v.w;
                        }
                    }
                    #pragma unroll
                    for (int q = 0; q < 8; ++q)
                        red_add_v4(gp + 4 * (qb + q), s[q].x, s[q].y, s[q].z, s[q].w);
                }
            }
        }
    }
}

// ---------------------------------------------------------------------------
// Node kernel (unchanged from passing R5/R8/R9 version)
// ---------------------------------------------------------------------------
#define NT   32
#define NTH  256
#define NO_W    0
#define NO_IN   40960
#define NO_B2A  51200
#define NO_B2B  51328
#define NO_IDX  51456
#define N_SMEM_BYTES ((51456 + NT) * 4)

__global__ void __launch_bounds__(NTH, 1)
node_kernel(const float* __restrict__ x_g,
            const float* __restrict__ u,
            const float* __restrict__ W2a, const float* __restrict__ b2a,
            const float* __restrict__ W2b, const float* __restrict__ b2b,
            const int* __restrict__ batch_g,
            float* __restrict__ out, int NG)
{
    extern __shared__ float sm[];
    float* Wt   = sm + NO_W;
    float* IN   = sm + NO_IN;
    float* sb2a = sm + NO_B2A;
    float* sb2b = sm + NO_B2B;
    int*   s_b  = reinterpret_cast<int*>(sm + NO_IDX);

    const int tid = threadIdx.x;
    const int n0 = blockIdx.x * NT;

    for (int t = tid; t < 128 * 320; t += NTH) {
        int j = t / 320, k = t % 320;
        Wt[k * 128 + j] = W2a[t];
    }
    if (tid < 128) { sb2a[tid] = b2a[tid]; sb2b[tid] = b2b[tid]; }
    if (tid < NT) {
        int n = n0 + tid;
        int b = 0;
        if (n < NG) {
            b = batch_g[n];
            if (b < 0) b = 0;
            if (b > 15) b = 15;
        }
        s_b[tid] = b;
    }
    __syncthreads();

    float4* IN4 = reinterpret_cast<float4*>(IN);
    const float4* Wt4 = reinterpret_cast<const float4*>(Wt);

    for (int f = tid; f < NT * 80; f += NTH) {
        int i = f / 80, c = f % 80;
        int n = n0 + i;
        float4 val = make_float4(0.f, 0.f, 0.f, 0.f);
        if (n < NG) {
            if (c < 32)
                val = reinterpret_cast<const float4*>(x_g)[(size_t)n * 32 + c];
            else if (c < 64)
                val = reinterpret_cast<const float4*>(g_accum)[(size_t)n * 32 + (c - 32)];
            else
                val = reinterpret_cast<const float4*>(u)[(size_t)s_b[i] * 16 + (c - 64)];
        }
        IN4[f] = val;
    }
    __syncthreads();

    const int w = tid >> 5;
    const int l = tid & 31;
    const int i0 = w * 4;
    const float4 ba = reinterpret_cast<const float4*>(sb2a)[l];
    const float4 bb = reinterpret_cast<const float4*>(sb2b)[l];

    float4 acc[4];
    #pragma unroll
    for (int i = 0; i < 4; ++i) acc[i] = ba;

    for (int k4 = 0; k4 < 80; ++k4) {
        float4 w0 = Wt4[(k4 * 4 + 0) * 32 + l];
        float4 w1 = Wt4[(k4 * 4 + 1) * 32 + l];
        float4 w2 = Wt4[(k4 * 4 + 2) * 32 + l];
        float4 w3 = Wt4[(k4 * 4 + 3) * 32 + l];
        #pragma unroll
        for (int i = 0; i < 4; ++i) {
            float4 v = IN4[(i0 + i) * 80 + k4];
            acc[i].x = fmaf(v.x, w0.x, acc[i].x); acc[i].y = fmaf(v.x, w0.y, acc[i].y);
            acc[i].z = fmaf(v.x, w0.z, acc[i].z); acc[i].w = fmaf(v.x, w0.w, acc[i].w);
            acc[i].x = fmaf(v.y, w1.x, acc[i].x); acc[i].y = fmaf(v.y, w1.y, acc[i].y);
            acc[i].z = fmaf(v.y, w1.z, acc[i].z); acc[i].w = fmaf(v.y, w1.w, acc[i].w);
            acc[i].x = fmaf(v.z, w2.x, acc[i].x); acc[i].y = fmaf(v.z, w2.y, acc[i].y);
            acc[i].z = fmaf(v.z, w2.z, acc[i].z); acc[i].w = fmaf(v.z, w2.w, acc[i].w);
            acc[i].x = fmaf(v.w, w3.x, acc[i].x); acc[i].y = fmaf(v.w, w3.y, acc[i].y);
            acc[i].z = fmaf(v.w, w3.z, acc[i].z); acc[i].w = fmaf(v.w, w3.w, acc[i].w);
        }
    }

    __syncwarp();
    #pragma unroll
    for (int i = 0; i < 4; ++i) {
        float4 h;
        h.x = lrelu(acc[i].x); h.y = lrelu(acc[i].y);
        h.z = lrelu(acc[i].z); h.w = lrelu(acc[i].w);
        IN4[(i0 + i) * 80 + l] = h;
    }
    __syncthreads();

    for (int t = tid; t < 128 * 128; t += NTH) {
        int j = t >> 7, k = t & 127;
        Wt[k * 128 + j] = W2b[t];
    }
    __syncthreads();

    #pragma unroll
    for (int i = 0; i < 4; ++i) acc[i] = bb;

    for (int k4 = 0; k4 < 32; ++k4) {
        float4 w0 = Wt4[(k4 * 4 + 0) * 32 + l];
        float4 w1 = Wt4[(k4 * 4 + 1) * 32 + l];
        float4 w2 = Wt4[(k4 * 4 + 2) * 32 + l];
        float4 w3 = Wt4[(k4 * 4 + 3) * 32 + l];
        #pragma unroll
        for (int i = 0; i < 4; ++i) {
            float4 v = IN4[(i0 + i) * 80 + k4];
            acc[i].x = fmaf(v.x, w0.x, acc[i].x); acc[i].y = fmaf(v.x, w0.y, acc[i].y);
            acc[i].z = fmaf(v.x, w0.z, acc[i].z); acc[i].w = fmaf(v.x, w0.w, acc[i].w);
            acc[i].x = fmaf(v.y, w1.x, acc[i].x); acc[i].y = fmaf(v.y, w1.y, acc[i].y);
            acc[i].z = fmaf(v.y, w1.z, acc[i].z); acc[i].w = fmaf(v.y, w1.w, acc[i].w);
            acc[i].x = fmaf(v.z, w2.x, acc[i].x); acc[i].y = fmaf(v.z, w2.y, acc[i].y);
            acc[i].z = fmaf(v.z, w2.z, acc[i].z); acc[i].w = fmaf(v.z, w2.w, acc[i].w);
            acc[i].x = fmaf(v.w, w3.x, acc[i].x); acc[i].y = fmaf(v.w, w3.y, acc[i].y);
            acc[i].z = fmaf(v.w, w3.z, acc[i].z); acc[i].w = fmaf(v.w, w3.w, acc[i].w);
        }
    }

    #pragma unroll
    for (int i = 0; i < 4; ++i) {
        int n = n0 + i0 + i;
        if (n < NG)
            reinterpret_cast<float4*>(out)[(size_t)n * 32 + l] = acc[i];
    }
}

// ---------------------------------------------------------------------------
// kernel_launch
// ---------------------------------------------------------------------------
extern "C" void kernel_launch(void* const* d_in, const int* in_sizes, int n_in,
                              void* d_out, int out_size) {
    const float* x_h       = (const float*)d_in[0];
    const float* x_g       = (const float*)d_in[1];
    const float* edge_attr = (const float*)d_in[2];
    const float* u         = (const float*)d_in[3];
    const float* W1a       = (const float*)d_in[4];
    const float* b1a       = (const float*)d_in[5];
    const float* W1b       = (const float*)d_in[6];
    const float* b1b       = (const float*)d_in[7];
    const float* W2a       = (const float*)d_in[8];
    const float* b2a       = (const float*)d_in[9];
    const float* W2b       = (const float*)d_in[10];
    const float* b2b       = (const float*)d_in[11];
    const int* eidx        = (const int*)d_in[12];
    const int* batch       = (const int*)d_in[13];
    float* out = (float*)d_out;

    const int E  = in_sizes[12] / 2;
    const int NG = in_sizes[1] / N_GC;

    cudaFuncSetAttribute(edge_kernel, cudaFuncAttributeMaxDynamicSharedMemorySize,
                         E_SMEM_BYTES);
    cudaFuncSetAttribute(node_kernel, cudaFuncAttributeMaxDynamicSharedMemorySize,
                         N_SMEM_BYTES);

    zero_accum_kernel<<<1024, 256>>>();
    hist_kernel<<<512, 256>>>(eidx, E);
    scan_kernel<<<1, 1024>>>();
    rank_scatter_kernel<<<512, 256>>>(eidx, E);
    edge_kernel<<<152, ETH, E_SMEM_BYTES>>>(x_h, edge_attr, W1a, b1a, W1b, b1b,
                                            eidx, E);
    int node_blocks = (NG + NT - 1) / NT;
    node_kernel<<<node_blocks, NTH, N_SMEM_BYTES>>>(x_g, u, W2a, b2a, W2b, b2b,
                                                    batch, out, NG);
}

// round 12
// speedup vs baseline: 1.9694x; 1.9694x over previous
#include <cuda_runtime.h>
#include <cuda_bf16.h>
#include <cstdint>

#define N_H_NODES 50000
#define N_G_NODES 50000
#define N_GC 128

// Scatter-sum accumulator: 25.6 MB static scratch, 128B aligned.
__device__ __align__(128) float g_accum[(size_t)N_G_NODES * N_GC];

__device__ __forceinline__ float lrelu(float v) { return v >= 0.0f ? v : 0.1f * v; }

// ---------------------------------------------------------------------------
// mma.sync / ldmatrix helpers (baseline PTX, compiles for compute_103)
// ---------------------------------------------------------------------------
__device__ __forceinline__ uint32_t smem_to_u32(const void* p) {
    uint32_t a;
    asm("{ .reg .u64 t; cvta.to.shared.u64 t, %1; cvt.u32.u64 %0, t; }" : "=r"(a) : "l"(p));
    return a;
}
__device__ __forceinline__ void ldsm4t(uint32_t b[4], uint32_t addr) {
    asm volatile("ldmatrix.sync.aligned.m8n8.x4.trans.shared.b16 {%0,%1,%2,%3}, [%4];"
                 : "=r"(b[0]), "=r"(b[1]), "=r"(b[2]), "=r"(b[3]) : "r"(addr));
}
__device__ __forceinline__ void mma16816(float d[4], const uint32_t a[4], const uint32_t b[2]) {
    asm volatile("mma.sync.aligned.m16n8k16.row.col.f32.bf16.bf16.f32 "
                 "{%0,%1,%2,%3}, {%4,%5,%6,%7}, {%8,%9}, {%0,%1,%2,%3};"
                 : "+f"(d[0]), "+f"(d[1]), "+f"(d[2]), "+f"(d[3])
                 : "r"(a[0]), "r"(a[1]), "r"(a[2]), "r"(a[3]), "r"(b[0]), "r"(b[1]));
}
__device__ __forceinline__ void bf16_split(float v, uint16_t& h, uint16_t& l) {
    __nv_bfloat16 hb = __float2bfloat16_rn(v);
    h = __bfloat16_as_ushort(hb);
    l = __bfloat16_as_ushort(__float2bfloat16_rn(v - __bfloat162float(hb)));
}
// pack two floats (consecutive cols) into bf16x2 hi/lo planes
__device__ __forceinline__ void pack2(float x, float y, uint32_t& hi, uint32_t& lo) {
    uint16_t h0, l0, h1, l1;
    bf16_split(x, h0, l0);
    bf16_split(y, h1, l1);
    hi = (uint32_t)h0 | ((uint32_t)h1 << 16);
    lo = (uint32_t)l0 | ((uint32_t)l1 << 16);
}
__device__ __forceinline__ void red_add_v2(float* p, float a, float b) {
    asm volatile("red.global.add.v2.f32 [%0], {%1, %2};" :: "l"(p), "f"(a), "f"(b) : "memory");
}

// ---------------------------------------------------------------------------
// zero accumulator
// ---------------------------------------------------------------------------
__global__ void zero_accum_kernel() {
    size_t n4 = (size_t)N_G_NODES * N_GC / 4;
    float4 z = make_float4(0.f, 0.f, 0.f, 0.f);
    float4* p = reinterpret_cast<float4*>(g_accum);
    for (size_t i = (size_t)blockIdx.x * blockDim.x + threadIdx.x; i < n4;
         i += (size_t)gridDim.x * blockDim.x)
        p[i] = z;
}

// ---------------------------------------------------------------------------
// Fused edge MLP: warp-autonomous, 512 threads (4 warps/SMSP), bf16x3.
//
// Each warp owns 16 edges per group (grid-strided over groups):
//   - A fragments gathered DIRECTLY from gmem (float2 per-lane loads matching
//     m16k16 fragment layout) -> no V SMEM, no ldsm for A, no block barriers.
//   - GEMM1 (n=128 in regs, 3-term bf16), register repack (lrelu+split) into
//     GEMM2 A-fragments, GEMM2 in two n-halves (register cap), scatter via
//     red.global.add.v2 straight from accumulators.
// SMEM: only the 4 transposed weight planes (Wt[k][n], PADK pad) + biases.
// ---------------------------------------------------------------------------
#define ETH   512
#define PADK  136
#define PLANE (128 * PADK * 2)     // 34816 bytes per bf16 plane

#define SO_WAHI 0
#define SO_WALO (SO_WAHI + PLANE)
#define SO_WBHI (SO_WALO + PLANE)
#define SO_WBLO (SO_WBHI + PLANE)
#define SO_B1A  (SO_WBLO + PLANE)   // float[128]
#define SO_B1B  (SO_B1A + 512)
#define E_SMEM_BYTES (SO_B1B + 512) // 140288

__global__ void __launch_bounds__(ETH, 1)
edge_kernel(const float* __restrict__ x_h,
            const float* __restrict__ edge_attr,
            const float* __restrict__ W1a, const float* __restrict__ b1a,
            const float* __restrict__ W1b, const float* __restrict__ b1b,
            const int* __restrict__ eidx, int E)
{
    extern __shared__ char smc[];
    const uint32_t sb = smem_to_u32(smc);
    uint16_t* WaHi = reinterpret_cast<uint16_t*>(smc + SO_WAHI);
    uint16_t* WaLo = reinterpret_cast<uint16_t*>(smc + SO_WALO);
    uint16_t* WbHi = reinterpret_cast<uint16_t*>(smc + SO_WBHI);
    uint16_t* WbLo = reinterpret_cast<uint16_t*>(smc + SO_WBLO);
    float* sb1a = reinterpret_cast<float*>(smc + SO_B1A);
    float* sb1b = reinterpret_cast<float*>(smc + SO_B1B);

    const int tid  = threadIdx.x;
    const int wid  = tid >> 5;
    const int lane = tid & 31;

    // Stage weights transposed + split: Wt[k][n] = W[n][k]
    for (int t = tid; t < 128 * 128; t += ETH) {
        int n = t >> 7, k = t & 127;
        uint16_t h, l;
        bf16_split(W1a[t], h, l);
        WaHi[k * PADK + n] = h; WaLo[k * PADK + n] = l;
        bf16_split(W1b[t], h, l);
        WbHi[k * PADK + n] = h; WbLo[k * PADK + n] = l;
    }
    if (tid < 128) { sb1a[tid] = b1a[tid]; sb1b[tid] = b1b[tid]; }
    __syncthreads();   // only block barrier in the kernel

    const int qr = lane >> 2;          // fragment row within m8  (0..7)
    const int qt = lane & 3;           // fragment col-pair selector (0..3)
    const uint32_t boff = ((uint32_t)(lane & 15) * PADK + (uint32_t)(lane >> 4) * 8) * 2;
    const uint32_t wahiA = sb + SO_WAHI, waloA = sb + SO_WALO;
    const uint32_t wbhiA = sb + SO_WBHI, wbloA = sb + SO_WBLO;

    const int* srcp = eidx;
    const int* tgtp = eidx + E;
    const int nGroups = (E + 15) >> 4;
    const int totalWarps = gridDim.x * (ETH / 32);

    for (int g = blockIdx.x * (ETH / 32) + wid; g < nGroups; g += totalWarps) {
        const int ebase = g * 16;

        // lanes 0-15 load this group's indices; distribute via shfl
        int my_src = 0, my_tgt = -1;
        if (lane < 16) {
            int e = ebase + lane;
            if (e < E) {
                int s = srcp[e], t = tgtp[e];
                if (s < 0) s = 0;
                if (s >= N_H_NODES) s = N_H_NODES - 1;
                if (t < 0 || t >= N_G_NODES) t = -1;
                my_src = s; my_tgt = t;
            }
        }
        const int src0 = __shfl_sync(0xFFFFFFFFu, my_src, qr);
        const int src1 = __shfl_sync(0xFFFFFFFFu, my_src, qr + 8);
        const int tgt0 = __shfl_sync(0xFFFFFFFFu, my_tgt, qr);
        const int tgt1 = __shfl_sync(0xFFFFFFFFu, my_tgt, qr + 8);
        const int e0 = min(ebase + qr, E - 1);
        const int e1 = min(ebase + qr + 8, E - 1);

        const float* r0x = x_h + (size_t)src0 * 64;
        const float* r1x = x_h + (size_t)src1 * 64;
        const float* r0e = edge_attr + (size_t)e0 * 64;
        const float* r1e = edge_attr + (size_t)e1 * 64;

        // --- GEMM 1: streamed A gather, acc over full n=128 ---
        float acc[16][4];
        #pragma unroll
        for (int j = 0; j < 16; ++j)
            #pragma unroll
            for (int q = 0; q < 4; ++q) acc[j][q] = 0.f;

        #pragma unroll
        for (int ks = 0; ks < 8; ++ks) {
            // A fragment: a0=(qr,c0) a1=(qr+8,c0) a2=(qr,c0+8) a3=(qr+8,c0+8)
            const int c0 = ks * 16 + 2 * qt;
            float2 v0, v1, v2, v3;
            if (ks < 4) {   // cols 0..63 from x_h
                v0 = *reinterpret_cast<const float2*>(r0x + c0);
                v1 = *reinterpret_cast<const float2*>(r1x + c0);
                v2 = *reinterpret_cast<const float2*>(r0x + c0 + 8);
                v3 = *reinterpret_cast<const float2*>(r1x + c0 + 8);
            } else {        // cols 64..127 from edge_attr
                const int cc = c0 - 64;
                v0 = *reinterpret_cast<const float2*>(r0e + cc);
                v1 = *reinterpret_cast<const float2*>(r1e + cc);
                v2 = *reinterpret_cast<const float2*>(r0e + cc + 8);
                v3 = *reinterpret_cast<const float2*>(r1e + cc + 8);
            }
            uint32_t ahi[4], alo[4];
            pack2(v0.x, v0.y, ahi[0], alo[0]);
            pack2(v1.x, v1.y, ahi[1], alo[1]);
            pack2(v2.x, v2.y, ahi[2], alo[2]);
            pack2(v3.x, v3.y, ahi[3], alo[3]);

            #pragma unroll
            for (int np = 0; np < 8; ++np) {
                uint32_t bh[4], bl[4];
                const uint32_t bb = (uint32_t)(ks * 16 * PADK + np * 16) * 2 + boff;
                ldsm4t(bh, wahiA + bb);
                ldsm4t(bl, waloA + bb);
                mma16816(acc[2 * np + 0], ahi, bh + 0);
                mma16816(acc[2 * np + 0], alo, bh + 0);
                mma16816(acc[2 * np + 0], ahi, bl + 0);
                mma16816(acc[2 * np + 1], ahi, bh + 2);
                mma16816(acc[2 * np + 1], alo, bh + 2);
                mma16816(acc[2 * np + 1], ahi, bl + 2);
            }
        }

        // Register epilogue: H = lrelu(acc + b1a), repacked as GEMM2 A-frags.
        // C(m16n8) {d0,d1;d2,d3} -> A(m16k16): j even -> {a0;a1}, j odd -> {a2;a3}
        uint32_t ah2[8][4], al2[8][4];
        #pragma unroll
        for (int j = 0; j < 16; ++j) {
            const int c = 8 * j + 2 * qt;
            const float2 bx = *reinterpret_cast<const float2*>(sb1a + c);
            const int ks2 = j >> 1;
            const int ix = (j & 1) * 2;
            pack2(lrelu(acc[j][0] + bx.x), lrelu(acc[j][1] + bx.y),
                  ah2[ks2][ix + 0], al2[ks2][ix + 0]);
            pack2(lrelu(acc[j][2] + bx.x), lrelu(acc[j][3] + bx.y),
                  ah2[ks2][ix + 1], al2[ks2][ix + 1]);
        }

        // --- GEMM 2 in two n-halves (register cap), scatter per half ---
        #pragma unroll
        for (int nh = 0; nh < 2; ++nh) {
            float a2[8][4];
            #pragma unroll
            for (int j = 0; j < 8; ++j)
                #pragma unroll
                for (int q = 0; q < 4; ++q) a2[j][q] = 0.f;

            #pragma unroll
            for (int ks = 0; ks < 8; ++ks) {
                #pragma unroll
                for (int np = 0; np < 4; ++np) {
                    uint32_t bh[4], bl[4];
                    const uint32_t bb =
                        (uint32_t)(ks * 16 * PADK + nh * 64 + np * 16) * 2 + boff;
                    ldsm4t(bh, wbhiA + bb);
                    ldsm4t(bl, wbloA + bb);
                    mma16816(a2[2 * np + 0], ah2[ks], bh + 0);
                    mma16816(a2[2 * np + 0], al2[ks], bh + 0);
                    mma16816(a2[2 * np + 0], ah2[ks], bl + 0);
                    mma16816(a2[2 * np + 1], ah2[ks], bh + 2);
                    mma16816(a2[2 * np + 1], al2[ks], bh + 2);
                    mma16816(a2[2 * np + 1], ah2[ks], bl + 2);
                }
            }

            // Scatter this half straight from accumulators
            #pragma unroll
            for (int nt = 0; nt < 8; ++nt) {
                const int c = nh * 64 + nt * 8 + 2 * qt;
                const float2 bx = *reinterpret_cast<const float2*>(sb1b + c);
                if (tgt0 >= 0)
                    red_add_v2(g_accum + (size_t)tgt0 * 128 + c,
                               a2[nt][0] + bx.x, a2[nt][1] + bx.y);
                if (tgt1 >= 0)
                    red_add_v2(g_accum + (size_t)tgt1 * 128 + c,
                               a2[nt][2] + bx.x, a2[nt][3] + bx.y);
            }
        }
    }
}

// ---------------------------------------------------------------------------
// Node kernel (unchanged from passing R5/R8/R9 version)
// ---------------------------------------------------------------------------
#define NT   32
#define NTH  256
#define NO_W    0
#define NO_IN   40960
#define NO_B2A  51200
#define NO_B2B  51328
#define NO_IDX  51456
#define N_SMEM_BYTES ((51456 + NT) * 4)

__global__ void __launch_bounds__(NTH, 1)
node_kernel(const float* __restrict__ x_g,
            const float* __restrict__ u,
            const float* __restrict__ W2a, const float* __restrict__ b2a,
            const float* __restrict__ W2b, const float* __restrict__ b2b,
            const int* __restrict__ batch_g,
            float* __restrict__ out, int NG)
{
    extern __shared__ float sm[];
    float* Wt   = sm + NO_W;
    float* IN   = sm + NO_IN;
    float* sb2a = sm + NO_B2A;
    float* sb2b = sm + NO_B2B;
    int*   s_b  = reinterpret_cast<int*>(sm + NO_IDX);

    const int tid = threadIdx.x;
    const int n0 = blockIdx.x * NT;

    for (int t = tid; t < 128 * 320; t += NTH) {
        int j = t / 320, k = t % 320;
        Wt[k * 128 + j] = W2a[t];
    }
    if (tid < 128) { sb2a[tid] = b2a[tid]; sb2b[tid] = b2b[tid]; }
    if (tid < NT) {
        int n = n0 + tid;
        int b = 0;
        if (n < NG) {
            b = batch_g[n];
            if (b < 0) b = 0;
            if (b > 15) b = 15;
        }
        s_b[tid] = b;
    }
    __syncthreads();

    float4* IN4 = reinterpret_cast<float4*>(IN);
    const float4* Wt4 = reinterpret_cast<const float4*>(Wt);

    for (int f = tid; f < NT * 80; f += NTH) {
        int i = f / 80, c = f % 80;
        int n = n0 + i;
        float4 val = make_float4(0.f, 0.f, 0.f, 0.f);
        if (n < NG) {
            if (c < 32)
                val = reinterpret_cast<const float4*>(x_g)[(size_t)n * 32 + c];
            else if (c < 64)
                val = reinterpret_cast<const float4*>(g_accum)[(size_t)n * 32 + (c - 32)];
            else
                val = reinterpret_cast<const float4*>(u)[(size_t)s_b[i] * 16 + (c - 64)];
        }
        IN4[f] = val;
    }
    __syncthreads();

    const int w = tid >> 5;
    const int l = tid & 31;
    const int i0 = w * 4;
    const float4 ba = reinterpret_cast<const float4*>(sb2a)[l];
    const float4 bb = reinterpret_cast<const float4*>(sb2b)[l];

    float4 acc[4];
    #pragma unroll
    for (int i = 0; i < 4; ++i) acc[i] = ba;

    for (int k4 = 0; k4 < 80; ++k4) {
        float4 w0 = Wt4[(k4 * 4 + 0) * 32 + l];
        float4 w1 = Wt4[(k4 * 4 + 1) * 32 + l];
        float4 w2 = Wt4[(k4 * 4 + 2) * 32 + l];
        float4 w3 = Wt4[(k4 * 4 + 3) * 32 + l];
        #pragma unroll
        for (int i = 0; i < 4; ++i) {
            float4 v = IN4[(i0 + i) * 80 + k4];
            acc[i].x = fmaf(v.x, w0.x, acc[i].x); acc[i].y = fmaf(v.x, w0.y, acc[i].y);
            acc[i].z = fmaf(v.x, w0.z, acc[i].z); acc[i].w = fmaf(v.x, w0.w, acc[i].w);
            acc[i].x = fmaf(v.y, w1.x, acc[i].x); acc[i].y = fmaf(v.y, w1.y, acc[i].y);
            acc[i].z = fmaf(v.y, w1.z, acc[i].z); acc[i].w = fmaf(v.y, w1.w, acc[i].w);
            acc[i].x = fmaf(v.z, w2.x, acc[i].x); acc[i].y = fmaf(v.z, w2.y, acc[i].y);
            acc[i].z = fmaf(v.z, w2.z, acc[i].z); acc[i].w = fmaf(v.z, w2.w, acc[i].w);
            acc[i].x = fmaf(v.w, w3.x, acc[i].x); acc[i].y = fmaf(v.w, w3.y, acc[i].y);
            acc[i].z = fmaf(v.w, w3.z, acc[i].z); acc[i].w = fmaf(v.w, w3.w, acc[i].w);
        }
    }

    __syncwarp();
    #pragma unroll
    for (int i = 0; i < 4; ++i) {
        float4 h;
        h.x = lrelu(acc[i].x); h.y = lrelu(acc[i].y);
        h.z = lrelu(acc[i].z); h.w = lrelu(acc[i].w);
        IN4[(i0 + i) * 80 + l] = h;
    }
    __syncthreads();

    for (int t = tid; t < 128 * 128; t += NTH) {
        int j = t >> 7, k = t & 127;
        Wt[k * 128 + j] = W2b[t];
    }
    __syncthreads();

    #pragma unroll
    for (int i = 0; i < 4; ++i) acc[i] = bb;

    for (int k4 = 0; k4 < 32; ++k4) {
        float4 w0 = Wt4[(k4 * 4 + 0) * 32 + l];
        float4 w1 = Wt4[(k4 * 4 + 1) * 32 + l];
        float4 w2 = Wt4[(k4 * 4 + 2) * 32 + l];
        float4 w3 = Wt4[(k4 * 4 + 3) * 32 + l];
        #pragma unroll
        for (int i = 0; i < 4; ++i) {
            float4 v = IN4[(i0 + i) * 80 + k4];
            acc[i].x = fmaf(v.x, w0.x, acc[i].x); acc[i].y = fmaf(v.x, w0.y, acc[i].y);
            acc[i].z = fmaf(v.x, w0.z, acc[i].z); acc[i].w = fmaf(v.x, w0.w, acc[i].w);
            acc[i].x = fmaf(v.y, w1.x, acc[i].x); acc[i].y = fmaf(v.y, w1.y, acc[i].y);
            acc[i].z = fmaf(v.y, w1.z, acc[i].z); acc[i].w = fmaf(v.y, w1.w, acc[i].w);
            acc[i].x = fmaf(v.z, w2.x, acc[i].x); acc[i].y = fmaf(v.z, w2.y, acc[i].y);
            acc[i].z = fmaf(v.z, w2.z, acc[i].z); acc[i].w = fmaf(v.z, w2.w, acc[i].w);
            acc[i].x = fmaf(v.w, w3.x, acc[i].x); acc[i].y = fmaf(v.w, w3.y, acc[i].y);
            acc[i].z = fmaf(v.w, w3.z, acc[i].z); acc[i].w = fmaf(v.w, w3.w, acc[i].w);
        }
    }

    #pragma unroll
    for (int i = 0; i < 4; ++i) {
        int n = n0 + i0 + i;
        if (n < NG)
            reinterpret_cast<float4*>(out)[(size_t)n * 32 + l] = acc[i];
    }
}

// ---------------------------------------------------------------------------
// kernel_launch
// Inputs: 0 x_h, 1 x_g, 2 edge_attr, 3 u, 4 W1a, 5 b1a, 6 W1b, 7 b1b,
//         8 W2a, 9 b2a, 10 W2b, 11 b2b, 12 edge_index (int32), 13 batch_g (int32)
// ---------------------------------------------------------------------------
extern "C" void kernel_launch(void* const* d_in, const int* in_sizes, int n_in,
                              void* d_out, int out_size) {
    const float* x_h       = (const float*)d_in[0];
    const float* x_g       = (const float*)d_in[1];
    const float* edge_attr = (const float*)d_in[2];
    const float* u         = (const float*)d_in[3];
    const float* W1a       = (const float*)d_in[4];
    const float* b1a       = (const float*)d_in[5];
    const float* W1b       = (const float*)d_in[6];
    const float* b1b       = (const float*)d_in[7];
    const float* W2a       = (const float*)d_in[8];
    const float* b2a       = (const float*)d_in[9];
    const float* W2b       = (const float*)d_in[10];
    const float* b2b       = (const float*)d_in[11];
    const int* eidx        = (const int*)d_in[12];
    const int* batch       = (const int*)d_in[13];
    float* out = (float*)d_out;

    const int E  = in_sizes[12] / 2;
    const int NG = in_sizes[1] / N_GC;

    cudaFuncSetAttribute(edge_kernel, cudaFuncAttributeMaxDynamicSharedMemorySize,
                         E_SMEM_BYTES);
    cudaFuncSetAttribute(node_kernel, cudaFuncAttributeMaxDynamicSharedMemorySize,
                         N_SMEM_BYTES);

    zero_accum_kernel<<<1024, 256>>>();
    edge_kernel<<<152, ETH, E_SMEM_BYTES>>>(x_h, edge_attr, W1a, b1a, W1b, b1b,
                                            eidx, E);
    int node_blocks = (NG + NT - 1) / NT;
    node_kernel<<<node_blocks, NTH, N_SMEM_BYTES>>>(x_g, u, W2a, b2a, W2b, b2b,
                                                    batch, out, NG);
}

// round 13
// speedup vs baseline: 2.1086x; 1.0707x over previous
#include <cuda_runtime.h>
#include <cuda_bf16.h>
#include <cuda_fp16.h>
#include <cstdint>

#define N_H_NODES 50000
#define N_G_NODES 50000
#define N_GC 128

// Scatter-sum accumulator: 25.6 MB static scratch, 128B aligned.
__device__ __align__(128) float g_accum[(size_t)N_G_NODES * N_GC];

__device__ __forceinline__ float lrelu(float v) { return v >= 0.0f ? v : 0.1f * v; }

// ---------------------------------------------------------------------------
// mma.sync / ldmatrix helpers (baseline PTX, compiles for compute_103)
// ---------------------------------------------------------------------------
__device__ __forceinline__ uint32_t smem_to_u32(const void* p) {
    uint32_t a;
    asm("{ .reg .u64 t; cvta.to.shared.u64 t, %1; cvt.u32.u64 %0, t; }" : "=r"(a) : "l"(p));
    return a;
}
__device__ __forceinline__ void ldsm4t(uint32_t b[4], uint32_t addr) {
    asm volatile("ldmatrix.sync.aligned.m8n8.x4.trans.shared.b16 {%0,%1,%2,%3}, [%4];"
                 : "=r"(b[0]), "=r"(b[1]), "=r"(b[2]), "=r"(b[3]) : "r"(addr));
}
// fp16 mma: D(f32) += A(f16) * B(f16)
__device__ __forceinline__ void mma16816h(float d[4], const uint32_t a[4], const uint32_t b[2]) {
    asm volatile("mma.sync.aligned.m16n8k16.row.col.f32.f16.f16.f32 "
                 "{%0,%1,%2,%3}, {%4,%5,%6,%7}, {%8,%9}, {%0,%1,%2,%3};"
                 : "+f"(d[0]), "+f"(d[1]), "+f"(d[2]), "+f"(d[3])
                 : "r"(a[0]), "r"(a[1]), "r"(a[2]), "r"(a[3]), "r"(b[0]), "r"(b[1]));
}
// split fp32 weight into fp16 hi + fp16 lo (residual): ~2^-22 combined error
__device__ __forceinline__ void f16_split(float v, uint16_t& h, uint16_t& l) {
    __half hh = __float2half_rn(v);
    h = __half_as_ushort(hh);
    l = __half_as_ushort(__float2half_rn(v - __half2float(hh)));
}
// pack two floats into one fp16x2 register
__device__ __forceinline__ uint32_t packh2(float x, float y) {
    __half2 h = __floats2half2_rn(x, y);
    return *reinterpret_cast<uint32_t*>(&h);
}
__device__ __forceinline__ void red_add_v2(float* p, float a, float b) {
    asm volatile("red.global.add.v2.f32 [%0], {%1, %2};" :: "l"(p), "f"(a), "f"(b) : "memory");
}

// ---------------------------------------------------------------------------
// zero accumulator
// ---------------------------------------------------------------------------
__global__ void zero_accum_kernel() {
    size_t n4 = (size_t)N_G_NODES * N_GC / 4;
    float4 z = make_float4(0.f, 0.f, 0.f, 0.f);
    float4* p = reinterpret_cast<float4*>(g_accum);
    for (size_t i = (size_t)blockIdx.x * blockDim.x + threadIdx.x; i < n4;
         i += (size_t)gridDim.x * blockDim.x)
        p[i] = z;
}

// ---------------------------------------------------------------------------
// Fused edge MLP: warp-autonomous, 512 threads (4 warps/SMSP), fp16 2-term.
//
//   D = A * Whi + A * Wlo   (A single fp16, W split fp16 hi/lo)
//   -> 512 HMMA per 16-edge group (was 768 with bf16x3): -33% on the
//      HMMA-throughput roofline identified in R12's post-mortem.
//
// Each warp owns 16 edges per group (grid-strided):
//   - A fragments gathered directly from gmem (float2 loads matching the
//     m16k16 fragment layout), converted with ONE cvt per pair.
//   - GEMM1 full-n in regs; register repack (lrelu + fp16 cvt) into GEMM2
//     A-fragments; GEMM2 in two n-halves; red.v2 scatter from accumulators.
// SMEM: 4 weight planes (WaHi/WaLo/WbHi/WbLo, fp16, transposed) + biases.
// ---------------------------------------------------------------------------
#define ETH   512
#define PADK  136
#define PLANE (128 * PADK * 2)     // 34816 bytes per fp16 plane

#define SO_WAHI 0
#define SO_WALO (SO_WAHI + PLANE)
#define SO_WBHI (SO_WALO + PLANE)
#define SO_WBLO (SO_WBHI + PLANE)
#define SO_B1A  (SO_WBLO + PLANE)   // float[128]
#define SO_B1B  (SO_B1A + 512)
#define E_SMEM_BYTES (SO_B1B + 512) // 140288

__global__ void __launch_bounds__(ETH, 1)
edge_kernel(const float* __restrict__ x_h,
            const float* __restrict__ edge_attr,
            const float* __restrict__ W1a, const float* __restrict__ b1a,
            const float* __restrict__ W1b, const float* __restrict__ b1b,
            const int* __restrict__ eidx, int E)
{
    extern __shared__ char smc[];
    const uint32_t sb = smem_to_u32(smc);
    uint16_t* WaHi = reinterpret_cast<uint16_t*>(smc + SO_WAHI);
    uint16_t* WaLo = reinterpret_cast<uint16_t*>(smc + SO_WALO);
    uint16_t* WbHi = reinterpret_cast<uint16_t*>(smc + SO_WBHI);
    uint16_t* WbLo = reinterpret_cast<uint16_t*>(smc + SO_WBLO);
    float* sb1a = reinterpret_cast<float*>(smc + SO_B1A);
    float* sb1b = reinterpret_cast<float*>(smc + SO_B1B);

    const int tid  = threadIdx.x;
    const int wid  = tid >> 5;
    const int lane = tid & 31;

    // Stage weights transposed + fp16-split: Wt[k][n] = W[n][k]
    for (int t = tid; t < 128 * 128; t += ETH) {
        int n = t >> 7, k = t & 127;
        uint16_t h, l;
        f16_split(W1a[t], h, l);
        WaHi[k * PADK + n] = h; WaLo[k * PADK + n] = l;
        f16_split(W1b[t], h, l);
        WbHi[k * PADK + n] = h; WbLo[k * PADK + n] = l;
    }
    if (tid < 128) { sb1a[tid] = b1a[tid]; sb1b[tid] = b1b[tid]; }
    __syncthreads();   // only block barrier in the kernel

    const int qr = lane >> 2;          // fragment row within m8  (0..7)
    const int qt = lane & 3;           // fragment col-pair selector (0..3)
    const uint32_t boff = ((uint32_t)(lane & 15) * PADK + (uint32_t)(lane >> 4) * 8) * 2;
    const uint32_t wahiA = sb + SO_WAHI, waloA = sb + SO_WALO;
    const uint32_t wbhiA = sb + SO_WBHI, wbloA = sb + SO_WBLO;

    const int* srcp = eidx;
    const int* tgtp = eidx + E;
    const int nGroups = (E + 15) >> 4;
    const int totalWarps = gridDim.x * (ETH / 32);

    for (int g = blockIdx.x * (ETH / 32) + wid; g < nGroups; g += totalWarps) {
        const int ebase = g * 16;

        // lanes 0-15 load this group's indices; distribute via shfl
        int my_src = 0, my_tgt = -1;
        if (lane < 16) {
            int e = ebase + lane;
            if (e < E) {
                int s = srcp[e], t = tgtp[e];
                if (s < 0) s = 0;
                if (s >= N_H_NODES) s = N_H_NODES - 1;
                if (t < 0 || t >= N_G_NODES) t = -1;
                my_src = s; my_tgt = t;
            }
        }
        const int src0 = __shfl_sync(0xFFFFFFFFu, my_src, qr);
        const int src1 = __shfl_sync(0xFFFFFFFFu, my_src, qr + 8);
        const int tgt0 = __shfl_sync(0xFFFFFFFFu, my_tgt, qr);
        const int tgt1 = __shfl_sync(0xFFFFFFFFu, my_tgt, qr + 8);
        const int e0 = min(ebase + qr, E - 1);
        const int e1 = min(ebase + qr + 8, E - 1);

        const float* r0x = x_h + (size_t)src0 * 64;
        const float* r1x = x_h + (size_t)src1 * 64;
        const float* r0e = edge_attr + (size_t)e0 * 64;
        const float* r1e = edge_attr + (size_t)e1 * 64;

        // --- GEMM 1: streamed A gather, acc over full n=128 ---
        float acc[16][4];
        #pragma unroll
        for (int j = 0; j < 16; ++j)
            #pragma unroll
            for (int q = 0; q < 4; ++q) acc[j][q] = 0.f;

        #pragma unroll
        for (int ks = 0; ks < 8; ++ks) {
            // A fragment: a0=(qr,c0) a1=(qr+8,c0) a2=(qr,c0+8) a3=(qr+8,c0+8)
            const int c0 = ks * 16 + 2 * qt;
            float2 v0, v1, v2, v3;
            if (ks < 4) {   // cols 0..63 from x_h
                v0 = *reinterpret_cast<const float2*>(r0x + c0);
                v1 = *reinterpret_cast<const float2*>(r1x + c0);
                v2 = *reinterpret_cast<const float2*>(r0x + c0 + 8);
                v3 = *reinterpret_cast<const float2*>(r1x + c0 + 8);
            } else {        // cols 64..127 from edge_attr
                const int cc = c0 - 64;
                v0 = *reinterpret_cast<const float2*>(r0e + cc);
                v1 = *reinterpret_cast<const float2*>(r1e + cc);
                v2 = *reinterpret_cast<const float2*>(r0e + cc + 8);
                v3 = *reinterpret_cast<const float2*>(r1e + cc + 8);
            }
            uint32_t a[4];
            a[0] = packh2(v0.x, v0.y);
            a[1] = packh2(v1.x, v1.y);
            a[2] = packh2(v2.x, v2.y);
            a[3] = packh2(v3.x, v3.y);

            #pragma unroll
            for (int np = 0; np < 8; ++np) {
                uint32_t bh[4], bl[4];
                const uint32_t bb = (uint32_t)(ks * 16 * PADK + np * 16) * 2 + boff;
                ldsm4t(bh, wahiA + bb);
                ldsm4t(bl, waloA + bb);
                mma16816h(acc[2 * np + 0], a, bh + 0);
                mma16816h(acc[2 * np + 0], a, bl + 0);
                mma16816h(acc[2 * np + 1], a, bh + 2);
                mma16816h(acc[2 * np + 1], a, bl + 2);
            }
        }

        // Register epilogue: H = lrelu(acc + b1a), repacked as GEMM2 A-frags.
        // C(m16n8) {d0,d1;d2,d3} -> A(m16k16): j even -> {a0;a1}, j odd -> {a2;a3}
        uint32_t ah2[8][4];
        #pragma unroll
        for (int j = 0; j < 16; ++j) {
            const int c = 8 * j + 2 * qt;
            const float2 bx = *reinterpret_cast<const float2*>(sb1a + c);
            const int ks2 = j >> 1;
            const int ix = (j & 1) * 2;
            ah2[ks2][ix + 0] = packh2(lrelu(acc[j][0] + bx.x), lrelu(acc[j][1] + bx.y));
            ah2[ks2][ix + 1] = packh2(lrelu(acc[j][2] + bx.x), lrelu(acc[j][3] + bx.y));
        }

        // --- GEMM 2 in two n-halves, scatter per half ---
        #pragma unroll
        for (int nh = 0; nh < 2; ++nh) {
            float a2[8][4];
            #pragma unroll
            for (int j = 0; j < 8; ++j)
                #pragma unroll
                for (int q = 0; q < 4; ++q) a2[j][q] = 0.f;

            #pragma unroll
            for (int ks = 0; ks < 8; ++ks) {
                #pragma unroll
                for (int np = 0; np < 4; ++np) {
                    uint32_t bh[4], bl[4];
                    const uint32_t bb =
                        (uint32_t)(ks * 16 * PADK + nh * 64 + np * 16) * 2 + boff;
                    ldsm4t(bh, wbhiA + bb);
                    ldsm4t(bl, wbloA + bb);
                    mma16816h(a2[2 * np + 0], ah2[ks], bh + 0);
                    mma16816h(a2[2 * np + 0], ah2[ks], bl + 0);
                    mma16816h(a2[2 * np + 1], ah2[ks], bh + 2);
                    mma16816h(a2[2 * np + 1], ah2[ks], bl + 2);
                }
            }

            // Scatter this half straight from accumulators
            #pragma unroll
            for (int nt = 0; nt < 8; ++nt) {
                const int c = nh * 64 + nt * 8 + 2 * qt;
                const float2 bx = *reinterpret_cast<const float2*>(sb1b + c);
                if (tgt0 >= 0)
                    red_add_v2(g_accum + (size_t)tgt0 * 128 + c,
                               a2[nt][0] + bx.x, a2[nt][1] + bx.y);
                if (tgt1 >= 0)
                    red_add_v2(g_accum + (size_t)tgt1 * 128 + c,
                               a2[nt][2] + bx.x, a2[nt][3] + bx.y);
            }
        }
    }
}

// ---------------------------------------------------------------------------
// Node kernel (unchanged from passing R5/R8/R9/R12 version)
// ---------------------------------------------------------------------------
#define NT   32
#define NTH  256
#define NO_W    0
#define NO_IN   40960
#define NO_B2A  51200
#define NO_B2B  51328
#define NO_IDX  51456
#define N_SMEM_BYTES ((51456 + NT) * 4)

__global__ void __launch_bounds__(NTH, 1)
node_kernel(const float* __restrict__ x_g,
            const float* __restrict__ u,
            const float* __restrict__ W2a, const float* __restrict__ b2a,
            const float* __restrict__ W2b, const float* __restrict__ b2b,
            const int* __restrict__ batch_g,
            float* __restrict__ out, int NG)
{
    extern __shared__ float sm[];
    float* Wt   = sm + NO_W;
    float* IN   = sm + NO_IN;
    float* sb2a = sm + NO_B2A;
    float* sb2b = sm + NO_B2B;
    int*   s_b  = reinterpret_cast<int*>(sm + NO_IDX);

    const int tid = threadIdx.x;
    const int n0 = blockIdx.x * NT;

    for (int t = tid; t < 128 * 320; t += NTH) {
        int j = t / 320, k = t % 320;
        Wt[k * 128 + j] = W2a[t];
    }
    if (tid < 128) { sb2a[tid] = b2a[tid]; sb2b[tid] = b2b[tid]; }
    if (tid < NT) {
        int n = n0 + tid;
        int b = 0;
        if (n < NG) {
            b = batch_g[n];
            if (b < 0) b = 0;
            if (b > 15) b = 15;
        }
        s_b[tid] = b;
    }
    __syncthreads();

    float4* IN4 = reinterpret_cast<float4*>(IN);
    const float4* Wt4 = reinterpret_cast<const float4*>(Wt);

    for (int f = tid; f < NT * 80; f += NTH) {
        int i = f / 80, c = f % 80;
        int n = n0 + i;
        float4 val = make_float4(0.f, 0.f, 0.f, 0.f);
        if (n < NG) {
            if (c < 32)
                val = reinterpret_cast<const float4*>(x_g)[(size_t)n * 32 + c];
            else if (c < 64)
                val = reinterpret_cast<const float4*>(g_accum)[(size_t)n * 32 + (c - 32)];
            else
                val = reinterpret_cast<const float4*>(u)[(size_t)s_b[i] * 16 + (c - 64)];
        }
        IN4[f] = val;
    }
    __syncthreads();

    const int w = tid >> 5;
    const int l = tid & 31;
    const int i0 = w * 4;
    const float4 ba = reinterpret_cast<const float4*>(sb2a)[l];
    const float4 bb = reinterpret_cast<const float4*>(sb2b)[l];

    float4 acc[4];
    #pragma unroll
    for (int i = 0; i < 4; ++i) acc[i] = ba;

    for (int k4 = 0; k4 < 80; ++k4) {
        float4 w0 = Wt4[(k4 * 4 + 0) * 32 + l];
        float4 w1 = Wt4[(k4 * 4 + 1) * 32 + l];
        float4 w2 = Wt4[(k4 * 4 + 2) * 32 + l];
        float4 w3 = Wt4[(k4 * 4 + 3) * 32 + l];
        #pragma unroll
        for (int i = 0; i < 4; ++i) {
            float4 v = IN4[(i0 + i) * 80 + k4];
            acc[i].x = fmaf(v.x, w0.x, acc[i].x); acc[i].y = fmaf(v.x, w0.y, acc[i].y);
            acc[i].z = fmaf(v.x, w0.z, acc[i].z); acc[i].w = fmaf(v.x, w0.w, acc[i].w);
            acc[i].x = fmaf(v.y, w1.x, acc[i].x); acc[i].y = fmaf(v.y, w1.y, acc[i].y);
            acc[i].z = fmaf(v.y, w1.z, acc[i].z); acc[i].w = fmaf(v.y, w1.w, acc[i].w);
            acc[i].x = fmaf(v.z, w2.x, acc[i].x); acc[i].y = fmaf(v.z, w2.y, acc[i].y);
            acc[i].z = fmaf(v.z, w2.z, acc[i].z); acc[i].w = fmaf(v.z, w2.w, acc[i].w);
            acc[i].x = fmaf(v.w, w3.x, acc[i].x); acc[i].y = fmaf(v.w, w3.y, acc[i].y);
            acc[i].z = fmaf(v.w, w3.z, acc[i].z); acc[i].w = fmaf(v.w, w3.w, acc[i].w);
        }
    }

    __syncwarp();
    #pragma unroll
    for (int i = 0; i < 4; ++i) {
        float4 h;
        h.x = lrelu(acc[i].x); h.y = lrelu(acc[i].y);
        h.z = lrelu(acc[i].z); h.w = lrelu(acc[i].w);
        IN4[(i0 + i) * 80 + l] = h;
    }
    __syncthreads();

    for (int t = tid; t < 128 * 128; t += NTH) {
        int j = t >> 7, k = t & 127;
        Wt[k * 128 + j] = W2b[t];
    }
    __syncthreads();

    #pragma unroll
    for (int i = 0; i < 4; ++i) acc[i] = bb;

    for (int k4 = 0; k4 < 32; ++k4) {
        float4 w0 = Wt4[(k4 * 4 + 0) * 32 + l];
        float4 w1 = Wt4[(k4 * 4 + 1) * 32 + l];
        float4 w2 = Wt4[(k4 * 4 + 2) * 32 + l];
        float4 w3 = Wt4[(k4 * 4 + 3) * 32 + l];
        #pragma unroll
        for (int i = 0; i < 4; ++i) {
            float4 v = IN4[(i0 + i) * 80 + k4];
            acc[i].x = fmaf(v.x, w0.x, acc[i].x); acc[i].y = fmaf(v.x, w0.y, acc[i].y);
            acc[i].z = fmaf(v.x, w0.z, acc[i].z); acc[i].w = fmaf(v.x, w0.w, acc[i].w);
            acc[i].x = fmaf(v.y, w1.x, acc[i].x); acc[i].y = fmaf(v.y, w1.y, acc[i].y);
            acc[i].z = fmaf(v.y, w1.z, acc[i].z); acc[i].w = fmaf(v.y, w1.w, acc[i].w);
            acc[i].x = fmaf(v.z, w2.x, acc[i].x); acc[i].y = fmaf(v.z, w2.y, acc[i].y);
            acc[i].z = fmaf(v.z, w2.z, acc[i].z); acc[i].w = fmaf(v.z, w2.w, acc[i].w);
            acc[i].x = fmaf(v.w, w3.x, acc[i].x); acc[i].y = fmaf(v.w, w3.y, acc[i].y);
            acc[i].z = fmaf(v.w, w3.z, acc[i].z); acc[i].w = fmaf(v.w, w3.w, acc[i].w);
        }
    }

    #pragma unroll
    for (int i = 0; i < 4; ++i) {
        int n = n0 + i0 + i;
        if (n < NG)
            reinterpret_cast<float4*>(out)[(size_t)n * 32 + l] = acc[i];
    }
}

// ---------------------------------------------------------------------------
// kernel_launch
// Inputs: 0 x_h, 1 x_g, 2 edge_attr, 3 u, 4 W1a, 5 b1a, 6 W1b, 7 b1b,
//         8 W2a, 9 b2a, 10 W2b, 11 b2b, 12 edge_index (int32), 13 batch_g (int32)
// ---------------------------------------------------------------------------
extern "C" void kernel_launch(void* const* d_in, const int* in_sizes, int n_in,
                              void* d_out, int out_size) {
    const float* x_h       = (const float*)d_in[0];
    const float* x_g       = (const float*)d_in[1];
    const float* edge_attr = (const float*)d_in[2];
    const float* u         = (const float*)d_in[3];
    const float* W1a       = (const float*)d_in[4];
    const float* b1a       = (const float*)d_in[5];
    const float* W1b       = (const float*)d_in[6];
    const float* b1b       = (const float*)d_in[7];
    const float* W2a       = (const float*)d_in[8];
    const float* b2a       = (const float*)d_in[9];
    const float* W2b       = (const float*)d_in[10];
    const float* b2b       = (const float*)d_in[11];
    const int* eidx        = (const int*)d_in[12];
    const int* batch       = (const int*)d_in[13];
    float* out = (float*)d_out;

    const int E  = in_sizes[12] / 2;
    const int NG = in_sizes[1] / N_GC;

    cudaFuncSetAttribute(edge_kernel, cudaFuncAttributeMaxDynamicSharedMemorySize,
                         E_SMEM_BYTES);
    cudaFuncSetAttribute(node_kernel, cudaFuncAttributeMaxDynamicSharedMemorySize,
                         N_SMEM_BYTES);

    zero_accum_kernel<<<1024, 256>>>();
    edge_kernel<<<152, ETH, E_SMEM_BYTES>>>(x_h, edge_attr, W1a, b1a, W1b, b1b,
                                            eidx, E);
    int node_blocks = (NG + NT - 1) / NT;
    node_kernel<<<node_blocks, NTH, N_SMEM_BYTES>>>(x_g, u, W2a, b2a, W2b, b2b,
                                                    batch, out, NG);
}

// round 16
// speedup vs baseline: 2.5011x; 1.1861x over previous
#include <cuda_runtime.h>
#include <cuda_bf16.h>
#include <cuda_fp16.h>
#include <cstdint>

#define N_H_NODES 50000
#define N_G_NODES 50000
#define N_GC 128

// Scatter-sum accumulator: 25.6 MB static scratch, 128B aligned.
__device__ __align__(128) float g_accum[(size_t)N_G_NODES * N_GC];

__device__ __forceinline__ float lrelu(float v) { return v >= 0.0f ? v : 0.1f * v; }

// ---------------------------------------------------------------------------
// mma.sync / ldmatrix helpers (baseline PTX, compiles for compute_103)
// ---------------------------------------------------------------------------
__device__ __forceinline__ uint32_t smem_to_u32(const void* p) {
    uint32_t a;
    asm("{ .reg .u64 t; cvta.to.shared.u64 t, %1; cvt.u32.u64 %0, t; }" : "=r"(a) : "l"(p));
    return a;
}
__device__ __forceinline__ void ldsm4t(uint32_t b[4], uint32_t addr) {
    asm volatile("ldmatrix.sync.aligned.m8n8.x4.trans.shared.b16 {%0,%1,%2,%3}, [%4];"
                 : "=r"(b[0]), "=r"(b[1]), "=r"(b[2]), "=r"(b[3]) : "r"(addr));
}
// fp16 mma: D(f32) += A(f16) * B(f16)
__device__ __forceinline__ void mma16816h(float d[4], const uint32_t a[4], const uint32_t b[2]) {
    asm volatile("mma.sync.aligned.m16n8k16.row.col.f32.f16.f16.f32 "
                 "{%0,%1,%2,%3}, {%4,%5,%6,%7}, {%8,%9}, {%0,%1,%2,%3};"
                 : "+f"(d[0]), "+f"(d[1]), "+f"(d[2]), "+f"(d[3])
                 : "r"(a[0]), "r"(a[1]), "r"(a[2]), "r"(a[3]), "r"(b[0]), "r"(b[1]));
}
// pack two floats into one fp16x2 register
__device__ __forceinline__ uint32_t packh2(float x, float y) {
    __half2 h = __floats2half2_rn(x, y);
    return *reinterpret_cast<uint32_t*>(&h);
}
__device__ __forceinline__ void red_add_v2(float* p, float a, float b) {
    asm volatile("red.global.add.v2.f32 [%0], {%1, %2};" :: "l"(p), "f"(a), "f"(b) : "memory");
}

// ---------------------------------------------------------------------------
// zero accumulator
// ---------------------------------------------------------------------------
__global__ void zero_accum_kernel() {
    size_t n4 = (size_t)N_G_NODES * N_GC / 4;
    float4 z = make_float4(0.f, 0.f, 0.f, 0.f);
    float4* p = reinterpret_cast<float4*>(g_accum);
    for (size_t i = (size_t)blockIdx.x * blockDim.x + threadIdx.x; i < n4;
         i += (size_t)gridDim.x * blockDim.x)
        p[i] = z;
}

// ---------------------------------------------------------------------------
// Fused edge MLP: warp-autonomous, 512 threads (4 warps/SMSP), pure fp16.
//
//   D = A * W   (A and W both single fp16; weight-quant error ~= the
//   unavoidable fp16 activation-quant error -> total rel_err ~1.5-3e-4)
//   -> 256 HMMA per 16-edge group (R13: 512; R12: 768). On the measured
//      t = HMMA*rt16 + overhead model this halves the dominant term.
//
// Each warp owns 16 edges per group (grid-strided):
//   - A fragments gathered directly from gmem (float2 loads matching the
//     m16k16 fragment layout), one cvt per pair.
//   - GEMM1 full-n in regs; register repack (lrelu + fp16 cvt) into GEMM2
//     A-fragments; GEMM2 in two n-halves; red.v2 scatter from accumulators.
// SMEM: 2 weight planes (Wa/Wb fp16, transposed, PADK pad) + biases = 70KB.
// ---------------------------------------------------------------------------
#define ETH   512
#define PADK  136
#define PLANE (128 * PADK * 2)     // 34816 bytes per fp16 plane

#define SO_WA   0
#define SO_WB   (SO_WA + PLANE)
#define SO_B1A  (SO_WB + PLANE)     // float[128]
#define SO_B1B  (SO_B1A + 512)
#define E_SMEM_BYTES (SO_B1B + 512) // 70656

__global__ void __launch_bounds__(ETH, 1)
edge_kernel(const float* __restrict__ x_h,
            const float* __restrict__ edge_attr,
            const float* __restrict__ W1a, const float* __restrict__ b1a,
            const float* __restrict__ W1b, const float* __restrict__ b1b,
            const int* __restrict__ eidx, int E)
{
    extern __shared__ char smc[];
    const uint32_t sb = smem_to_u32(smc);
    uint16_t* Wa = reinterpret_cast<uint16_t*>(smc + SO_WA);
    uint16_t* Wb = reinterpret_cast<uint16_t*>(smc + SO_WB);
    float* sb1a = reinterpret_cast<float*>(smc + SO_B1A);
    float* sb1b = reinterpret_cast<float*>(smc + SO_B1B);

    const int tid  = threadIdx.x;
    const int wid  = tid >> 5;
    const int lane = tid & 31;

    // Stage weights transposed + fp16: Wt[k][n] = W[n][k]
    for (int t = tid; t < 128 * 128; t += ETH) {
        int n = t >> 7, k = t & 127;
        Wa[k * PADK + n] = __half_as_ushort(__float2half_rn(W1a[t]));
        Wb[k * PADK + n] = __half_as_ushort(__float2half_rn(W1b[t]));
    }
    if (tid < 128) { sb1a[tid] = b1a[tid]; sb1b[tid] = b1b[tid]; }
    __syncthreads();   // only block barrier in the kernel

    const int qr = lane >> 2;          // fragment row within m8  (0..7)
    const int qt = lane & 3;           // fragment col-pair selector (0..3)
    const uint32_t boff = ((uint32_t)(lane & 15) * PADK + (uint32_t)(lane >> 4) * 8) * 2;
    const uint32_t waA = sb + SO_WA, wbA = sb + SO_WB;

    const int* srcp = eidx;
    const int* tgtp = eidx + E;
    const int nGroups = (E + 15) >> 4;
    const int totalWarps = gridDim.x * (ETH / 32);

    for (int g = blockIdx.x * (ETH / 32) + wid; g < nGroups; g += totalWarps) {
        const int ebase = g * 16;

        // lanes 0-15 load this group's indices; distribute via shfl
        int my_src = 0, my_tgt = -1;
        if (lane < 16) {
            int e = ebase + lane;
            if (e < E) {
                int s = srcp[e], t = tgtp[e];
                if (s < 0) s = 0;
                if (s >= N_H_NODES) s = N_H_NODES - 1;
                if (t < 0 || t >= N_G_NODES) t = -1;
                my_src = s; my_tgt = t;
            }
        }
        const int src0 = __shfl_sync(0xFFFFFFFFu, my_src, qr);
        const int src1 = __shfl_sync(0xFFFFFFFFu, my_src, qr + 8);
        const int tgt0 = __shfl_sync(0xFFFFFFFFu, my_tgt, qr);
        const int tgt1 = __shfl_sync(0xFFFFFFFFu, my_tgt, qr + 8);
        const int e0 = min(ebase + qr, E - 1);
        const int e1 = min(ebase + qr + 8, E - 1);

        const float* r0x = x_h + (size_t)src0 * 64;
        const float* r1x = x_h + (size_t)src1 * 64;
        const float* r0e = edge_attr + (size_t)e0 * 64;
        const float* r1e = edge_attr + (size_t)e1 * 64;

        // --- GEMM 1: streamed A gather, acc over full n=128 ---
        float acc[16][4];
        #pragma unroll
        for (int j = 0; j < 16; ++j)
            #pragma unroll
            for (int q = 0; q < 4; ++q) acc[j][q] = 0.f;

        #pragma unroll
        for (int ks = 0; ks < 8; ++ks) {
            // A fragment: a0=(qr,c0) a1=(qr+8,c0) a2=(qr,c0+8) a3=(qr+8,c0+8)
            const int c0 = ks * 16 + 2 * qt;
            float2 v0, v1, v2, v3;
            if (ks < 4) {   // cols 0..63 from x_h
                v0 = *reinterpret_cast<const float2*>(r0x + c0);
                v1 = *reinterpret_cast<const float2*>(r1x + c0);
                v2 = *reinterpret_cast<const float2*>(r0x + c0 + 8);
                v3 = *reinterpret_cast<const float2*>(r1x + c0 + 8);
            } else {        // cols 64..127 from edge_attr
                const int cc = c0 - 64;
                v0 = *reinterpret_cast<const float2*>(r0e + cc);
                v1 = *reinterpret_cast<const float2*>(r1e + cc);
                v2 = *reinterpret_cast<const float2*>(r0e + cc + 8);
                v3 = *reinterpret_cast<const float2*>(r1e + cc + 8);
            }
            uint32_t a[4];
            a[0] = packh2(v0.x, v0.y);
            a[1] = packh2(v1.x, v1.y);
            a[2] = packh2(v2.x, v2.y);
            a[3] = packh2(v3.x, v3.y);

            #pragma unroll
            for (int np = 0; np < 8; ++np) {
                uint32_t bh[4];
                const uint32_t bb = (uint32_t)(ks * 16 * PADK + np * 16) * 2 + boff;
                ldsm4t(bh, waA + bb);
                mma16816h(acc[2 * np + 0], a, bh + 0);
                mma16816h(acc[2 * np + 1], a, bh + 2);
            }
        }

        // Register epilogue: H = lrelu(acc + b1a), repacked as GEMM2 A-frags.
        // C(m16n8) {d0,d1;d2,d3} -> A(m16k16): j even -> {a0;a1}, j odd -> {a2;a3}
        uint32_t ah2[8][4];
        #pragma unroll
        for (int j = 0; j < 16; ++j) {
            const int c = 8 * j + 2 * qt;
            const float2 bx = *reinterpret_cast<const float2*>(sb1a + c);
            const int ks2 = j >> 1;
            const int ix = (j & 1) * 2;
            ah2[ks2][ix + 0] = packh2(lrelu(acc[j][0] + bx.x), lrelu(acc[j][1] + bx.y));
            ah2[ks2][ix + 1] = packh2(lrelu(acc[j][2] + bx.x), lrelu(acc[j][3] + bx.y));
        }

        // --- GEMM 2 in two n-halves, scatter per half ---
        #pragma unroll
        for (int nh = 0; nh < 2; ++nh) {
            float a2[8][4];
            #pragma unroll
            for (int j = 0; j < 8; ++j)
                #pragma unroll
                for (int q = 0; q < 4; ++q) a2[j][q] = 0.f;

            #pragma unroll
            for (int ks = 0; ks < 8; ++ks) {
                #pragma unroll
                for (int np = 0; np < 4; ++np) {
                    uint32_t bh[4];
                    const uint32_t bb =
                        (uint32_t)(ks * 16 * PADK + nh * 64 + np * 16) * 2 + boff;
                    ldsm4t(bh, wbA + bb);
                    mma16816h(a2[2 * np + 0], ah2[ks], bh + 0);
                    mma16816h(a2[2 * np + 1], ah2[ks], bh + 2);
                }
            }

            // Scatter this half straight from accumulators
            #pragma unroll
            for (int nt = 0; nt < 8; ++nt) {
                const int c = nh * 64 + nt * 8 + 2 * qt;
                const float2 bx = *reinterpret_cast<const float2*>(sb1b + c);
                if (tgt0 >= 0)
                    red_add_v2(g_accum + (size_t)tgt0 * 128 + c,
                               a2[nt][0] + bx.x, a2[nt][1] + bx.y);
                if (tgt1 >= 0)
                    red_add_v2(g_accum + (size_t)tgt1 * 128 + c,
                               a2[nt][2] + bx.x, a2[nt][3] + bx.y);
            }
        }
    }
}

// ---------------------------------------------------------------------------
// Node kernel (unchanged from passing R5/R8/R9/R12/R13 version)
// ---------------------------------------------------------------------------
#define NT   32
#define NTH  256
#define NO_W    0
#define NO_IN   40960
#define NO_B2A  51200
#define NO_B2B  51328
#define NO_IDX  51456
#define N_SMEM_BYTES ((51456 + NT) * 4)

__global__ void __launch_bounds__(NTH, 1)
node_kernel(const float* __restrict__ x_g,
            const float* __restrict__ u,
            const float* __restrict__ W2a, const float* __restrict__ b2a,
            const float* __restrict__ W2b, const float* __restrict__ b2b,
            const int* __restrict__ batch_g,
            float* __restrict__ out, int NG)
{
    extern __shared__ float sm[];
    float* Wt   = sm + NO_W;
    float* IN   = sm + NO_IN;
    float* sb2a = sm + NO_B2A;
    float* sb2b = sm + NO_B2B;
    int*   s_b  = reinterpret_cast<int*>(sm + NO_IDX);

    const int tid = threadIdx.x;
    const int n0 = blockIdx.x * NT;

    for (int t = tid; t < 128 * 320; t += NTH) {
        int j = t / 320, k = t % 320;
        Wt[k * 128 + j] = W2a[t];
    }
    if (tid < 128) { sb2a[tid] = b2a[tid]; sb2b[tid] = b2b[tid]; }
    if (tid < NT) {
        int n = n0 + tid;
        int b = 0;
        if (n < NG) {
            b = batch_g[n];
            if (b < 0) b = 0;
            if (b > 15) b = 15;
        }
        s_b[tid] = b;
    }
    __syncthreads();

    float4* IN4 = reinterpret_cast<float4*>(IN);
    const float4* Wt4 = reinterpret_cast<const float4*>(Wt);

    for (int f = tid; f < NT * 80; f += NTH) {
        int i = f / 80, c = f % 80;
        int n = n0 + i;
        float4 val = make_float4(0.f, 0.f, 0.f, 0.f);
        if (n < NG) {
            if (c < 32)
                val = reinterpret_cast<const float4*>(x_g)[(size_t)n * 32 + c];
            else if (c < 64)
                val = reinterpret_cast<const float4*>(g_accum)[(size_t)n * 32 + (c - 32)];
            else
                val = reinterpret_cast<const float4*>(u)[(size_t)s_b[i] * 16 + (c - 64)];
        }
        IN4[f] = val;
    }
    __syncthreads();

    const int w = tid >> 5;
    const int l = tid & 31;
    const int i0 = w * 4;
    const float4 ba = reinterpret_cast<const float4*>(sb2a)[l];
    const float4 bb = reinterpret_cast<const float4*>(sb2b)[l];

    float4 acc[4];
    #pragma unroll
    for (int i = 0; i < 4; ++i) acc[i] = ba;

    for (int k4 = 0; k4 < 80; ++k4) {
        float4 w0 = Wt4[(k4 * 4 + 0) * 32 + l];
        float4 w1 = Wt4[(k4 * 4 + 1) * 32 + l];
        float4 w2 = Wt4[(k4 * 4 + 2) * 32 + l];
        float4 w3 = Wt4[(k4 * 4 + 3) * 32 + l];
        #pragma unroll
        for (int i = 0; i < 4; ++i) {
            float4 v = IN4[(i0 + i) * 80 + k4];
            acc[i].x = fmaf(v.x, w0.x, acc[i].x); acc[i].y = fmaf(v.x, w0.y, acc[i].y);
            acc[i].z = fmaf(v.x, w0.z, acc[i].z); acc[i].w = fmaf(v.x, w0.w, acc[i].w);
            acc[i].x = fmaf(v.y, w1.x, acc[i].x); acc[i].y = fmaf(v.y, w1.y, acc[i].y);
            acc[i].z = fmaf(v.y, w1.z, acc[i].z); acc[i].w = fmaf(v.y, w1.w, acc[i].w);
            acc[i].x = fmaf(v.z, w2.x, acc[i].x); acc[i].y = fmaf(v.z, w2.y, acc[i].y);
            acc[i].z = fmaf(v.z, w2.z, acc[i].z); acc[i].w = fmaf(v.z, w2.w, acc[i].w);
            acc[i].x = fmaf(v.w, w3.x, acc[i].x); acc[i].y = fmaf(v.w, w3.y, acc[i].y);
            acc[i].z = fmaf(v.w, w3.z, acc[i].z); acc[i].w = fmaf(v.w, w3.w, acc[i].w);
        }
    }

    __syncwarp();
    #pragma unroll
    for (int i = 0; i < 4; ++i) {
        float4 h;
        h.x = lrelu(acc[i].x); h.y = lrelu(acc[i].y);
        h.z = lrelu(acc[i].z); h.w = lrelu(acc[i].w);
        IN4[(i0 + i) * 80 + l] = h;
    }
    __syncthreads();

    for (int t = tid; t < 128 * 128; t += NTH) {
        int j = t >> 7, k = t & 127;
        Wt[k * 128 + j] = W2b[t];
    }
    __syncthreads();

    #pragma unroll
    for (int i = 0; i < 4; ++i) acc[i] = bb;

    for (int k4 = 0; k4 < 32; ++k4) {
        float4 w0 = Wt4[(k4 * 4 + 0) * 32 + l];
        float4 w1 = Wt4[(k4 * 4 + 1) * 32 + l];
        float4 w2 = Wt4[(k4 * 4 + 2) * 32 + l];
        float4 w3 = Wt4[(k4 * 4 + 3) * 32 + l];
        #pragma unroll
        for (int i = 0; i < 4; ++i) {
            float4 v = IN4[(i0 + i) * 80 + k4];
            acc[i].x = fmaf(v.x, w0.x, acc[i].x); acc[i].y = fmaf(v.x, w0.y, acc[i].y);
            acc[i].z = fmaf(v.x, w0.z, acc[i].z); acc[i].w = fmaf(v.x, w0.w, acc[i].w);
            acc[i].x = fmaf(v.y, w1.x, acc[i].x); acc[i].y = fmaf(v.y, w1.y, acc[i].y);
            acc[i].z = fmaf(v.y, w1.z, acc[i].z); acc[i].w = fmaf(v.y, w1.w, acc[i].w);
            acc[i].x = fmaf(v.z, w2.x, acc[i].x); acc[i].y = fmaf(v.z, w2.y, acc[i].y);
            acc[i].z = fmaf(v.z, w2.z, acc[i].z); acc[i].w = fmaf(v.z, w2.w, acc[i].w);
            acc[i].x = fmaf(v.w, w3.x, acc[i].x); acc[i].y = fmaf(v.w, w3.y, acc[i].y);
            acc[i].z = fmaf(v.w, w3.z, acc[i].z); acc[i].w = fmaf(v.w, w3.w, acc[i].w);
        }
    }

    #pragma unroll
    for (int i = 0; i < 4; ++i) {
        int n = n0 + i0 + i;
        if (n < NG)
            reinterpret_cast<float4*>(out)[(size_t)n * 32 + l] = acc[i];
    }
}

// ---------------------------------------------------------------------------
// kernel_launch
// Inputs: 0 x_h, 1 x_g, 2 edge_attr, 3 u, 4 W1a, 5 b1a, 6 W1b, 7 b1b,
//         8 W2a, 9 b2a, 10 W2b, 11 b2b, 12 edge_index (int32), 13 batch_g (int32)
// ---------------------------------------------------------------------------
extern "C" void kernel_launch(void* const* d_in, const int* in_sizes, int n_in,
                              void* d_out, int out_size) {
    const float* x_h       = (const float*)d_in[0];
    const float* x_g       = (const float*)d_in[1];
    const float* edge_attr = (const float*)d_in[2];
    const float* u         = (const float*)d_in[3];
    const float* W1a       = (const float*)d_in[4];
    const float* b1a       = (const float*)d_in[5];
    const float* W1b       = (const float*)d_in[6];
    const float* b1b       = (const float*)d_in[7];
    const float* W2a       = (const float*)d_in[8];
    const float* b2a       = (const float*)d_in[9];
    const float* W2b       = (const float*)d_in[10];
    const float* b2b       = (const float*)d_in[11];
    const int* eidx        = (const int*)d_in[12];
    const int* batch       = (const int*)d_in[13];
    float* out = (float*)d_out;

    const int E  = in_sizes[12] / 2;
    const int NG = in_sizes[1] / N_GC;

    cudaFuncSetAttribute(edge_kernel, cudaFuncAttributeMaxDynamicSharedMemorySize,
                         E_SMEM_BYTES);
    cudaFuncSetAttribute(node_kernel, cudaFuncAttributeMaxDynamicSharedMemorySize,
                         N_SMEM_BYTES);

    zero_accum_kernel<<<1024, 256>>>();
    edge_kernel<<<152, ETH, E_SMEM_BYTES>>>(x_h, edge_attr, W1a, b1a, W1b, b1b,
                                            eidx, E);
    int node_blocks = (NG + NT - 1) / NT;
    node_kernel<<<node_blocks, NTH, N_SMEM_BYTES>>>(x_g, u, W2a, b2a, W2b, b2b,
                                                    batch, out, NG);
}

// round 17
// speedup vs baseline: 5.0711x; 2.0276x over previous
#include <cuda_runtime.h>
#include <cuda_bf16.h>
#include <cuda_fp16.h>
#include <cstdint>

#define N_H_NODES 50000
#define N_G_NODES 50000
#define N_GC 128

// Scatter-sum accumulator: 25.6 MB static scratch, 128B aligned.
__device__ __align__(128) float g_accum[(size_t)N_G_NODES * N_GC];

__device__ __forceinline__ float lrelu(float v) { return v >= 0.0f ? v : 0.1f * v; }

// ---------------------------------------------------------------------------
// mma.sync / ldmatrix helpers (baseline PTX, compiles for compute_103)
// ---------------------------------------------------------------------------
__device__ __forceinline__ uint32_t smem_to_u32(const void* p) {
    uint32_t a;
    asm("{ .reg .u64 t; cvta.to.shared.u64 t, %1; cvt.u32.u64 %0, t; }" : "=r"(a) : "l"(p));
    return a;
}
__device__ __forceinline__ void ldsm4t(uint32_t b[4], uint32_t addr) {
    asm volatile("ldmatrix.sync.aligned.m8n8.x4.trans.shared.b16 {%0,%1,%2,%3}, [%4];"
                 : "=r"(b[0]), "=r"(b[1]), "=r"(b[2]), "=r"(b[3]) : "r"(addr));
}
// fp16 mma: D(f32) += A(f16) * B(f16)
__device__ __forceinline__ void mma16816h(float d[4], const uint32_t a[4], const uint32_t b[2]) {
    asm volatile("mma.sync.aligned.m16n8k16.row.col.f32.f16.f16.f32 "
                 "{%0,%1,%2,%3}, {%4,%5,%6,%7}, {%8,%9}, {%0,%1,%2,%3};"
                 : "+f"(d[0]), "+f"(d[1]), "+f"(d[2]), "+f"(d[3])
                 : "r"(a[0]), "r"(a[1]), "r"(a[2]), "r"(a[3]), "r"(b[0]), "r"(b[1]));
}
// pack two floats into one fp16x2 register
__device__ __forceinline__ uint32_t packh2(float x, float y) {
    __half2 h = __floats2half2_rn(x, y);
    return *reinterpret_cast<uint32_t*>(&h);
}
__device__ __forceinline__ void red_add_v2(float* p, float a, float b) {
    asm volatile("red.global.add.v2.f32 [%0], {%1, %2};" :: "l"(p), "f"(a), "f"(b) : "memory");
}

// ---------------------------------------------------------------------------
// zero accumulator
// ---------------------------------------------------------------------------
__global__ void zero_accum_kernel() {
    size_t n4 = (size_t)N_G_NODES * N_GC / 4;
    float4 z = make_float4(0.f, 0.f, 0.f, 0.f);
    float4* p = reinterpret_cast<float4*>(g_accum);
    for (size_t i = (size_t)blockIdx.x * blockDim.x + threadIdx.x; i < n4;
         i += (size_t)gridDim.x * blockDim.x)
        p[i] = z;
}

// ---------------------------------------------------------------------------
// Fused edge MLP: warp-autonomous, 512 threads (4 warps/SMSP), pure fp16.
// (unchanged from R16 passing version)
// ---------------------------------------------------------------------------
#define ETH   512
#define PADK  136
#define PLANE (128 * PADK * 2)     // 34816 bytes per fp16 plane

#define SO_WA   0
#define SO_WB   (SO_WA + PLANE)
#define SO_B1A  (SO_WB + PLANE)     // float[128]
#define SO_B1B  (SO_B1A + 512)
#define E_SMEM_BYTES (SO_B1B + 512) // 70656

__global__ void __launch_bounds__(ETH, 1)
edge_kernel(const float* __restrict__ x_h,
            const float* __restrict__ edge_attr,
            const float* __restrict__ W1a, const float* __restrict__ b1a,
            const float* __restrict__ W1b, const float* __restrict__ b1b,
            const int* __restrict__ eidx, int E)
{
    extern __shared__ char smc[];
    const uint32_t sb = smem_to_u32(smc);
    uint16_t* Wa = reinterpret_cast<uint16_t*>(smc + SO_WA);
    uint16_t* Wb = reinterpret_cast<uint16_t*>(smc + SO_WB);
    float* sb1a = reinterpret_cast<float*>(smc + SO_B1A);
    float* sb1b = reinterpret_cast<float*>(smc + SO_B1B);

    const int tid  = threadIdx.x;
    const int wid  = tid >> 5;
    const int lane = tid & 31;

    // Stage weights transposed + fp16: Wt[k][n] = W[n][k]
    for (int t = tid; t < 128 * 128; t += ETH) {
        int n = t >> 7, k = t & 127;
        Wa[k * PADK + n] = __half_as_ushort(__float2half_rn(W1a[t]));
        Wb[k * PADK + n] = __half_as_ushort(__float2half_rn(W1b[t]));
    }
    if (tid < 128) { sb1a[tid] = b1a[tid]; sb1b[tid] = b1b[tid]; }
    __syncthreads();   // only block barrier in the kernel

    const int qr = lane >> 2;          // fragment row within m8  (0..7)
    const int qt = lane & 3;           // fragment col-pair selector (0..3)
    const uint32_t boff = ((uint32_t)(lane & 15) * PADK + (uint32_t)(lane >> 4) * 8) * 2;
    const uint32_t waA = sb + SO_WA, wbA = sb + SO_WB;

    const int* srcp = eidx;
    const int* tgtp = eidx + E;
    const int nGroups = (E + 15) >> 4;
    const int totalWarps = gridDim.x * (ETH / 32);

    for (int g = blockIdx.x * (ETH / 32) + wid; g < nGroups; g += totalWarps) {
        const int ebase = g * 16;

        // lanes 0-15 load this group's indices; distribute via shfl
        int my_src = 0, my_tgt = -1;
        if (lane < 16) {
            int e = ebase + lane;
            if (e < E) {
                int s = srcp[e], t = tgtp[e];
                if (s < 0) s = 0;
                if (s >= N_H_NODES) s = N_H_NODES - 1;
                if (t < 0 || t >= N_G_NODES) t = -1;
                my_src = s; my_tgt = t;
            }
        }
        const int src0 = __shfl_sync(0xFFFFFFFFu, my_src, qr);
        const int src1 = __shfl_sync(0xFFFFFFFFu, my_src, qr + 8);
        const int tgt0 = __shfl_sync(0xFFFFFFFFu, my_tgt, qr);
        const int tgt1 = __shfl_sync(0xFFFFFFFFu, my_tgt, qr + 8);
        const int e0 = min(ebase + qr, E - 1);
        const int e1 = min(ebase + qr + 8, E - 1);

        const float* r0x = x_h + (size_t)src0 * 64;
        const float* r1x = x_h + (size_t)src1 * 64;
        const float* r0e = edge_attr + (size_t)e0 * 64;
        const float* r1e = edge_attr + (size_t)e1 * 64;

        // --- GEMM 1: streamed A gather, acc over full n=128 ---
        float acc[16][4];
        #pragma unroll
        for (int j = 0; j < 16; ++j)
            #pragma unroll
            for (int q = 0; q < 4; ++q) acc[j][q] = 0.f;

        #pragma unroll
        for (int ks = 0; ks < 8; ++ks) {
            // A fragment: a0=(qr,c0) a1=(qr+8,c0) a2=(qr,c0+8) a3=(qr+8,c0+8)
            const int c0 = ks * 16 + 2 * qt;
            float2 v0, v1, v2, v3;
            if (ks < 4) {   // cols 0..63 from x_h
                v0 = *reinterpret_cast<const float2*>(r0x + c0);
                v1 = *reinterpret_cast<const float2*>(r1x + c0);
                v2 = *reinterpret_cast<const float2*>(r0x + c0 + 8);
                v3 = *reinterpret_cast<const float2*>(r1x + c0 + 8);
            } else {        // cols 64..127 from edge_attr
                const int cc = c0 - 64;
                v0 = *reinterpret_cast<const float2*>(r0e + cc);
                v1 = *reinterpret_cast<const float2*>(r1e + cc);
                v2 = *reinterpret_cast<const float2*>(r0e + cc + 8);
                v3 = *reinterpret_cast<const float2*>(r1e + cc + 8);
            }
            uint32_t a[4];
            a[0] = packh2(v0.x, v0.y);
            a[1] = packh2(v1.x, v1.y);
            a[2] = packh2(v2.x, v2.y);
            a[3] = packh2(v3.x, v3.y);

            #pragma unroll
            for (int np = 0; np < 8; ++np) {
                uint32_t bh[4];
                const uint32_t bb = (uint32_t)(ks * 16 * PADK + np * 16) * 2 + boff;
                ldsm4t(bh, waA + bb);
                mma16816h(acc[2 * np + 0], a, bh + 0);
                mma16816h(acc[2 * np + 1], a, bh + 2);
            }
        }

        // Register epilogue: H = lrelu(acc + b1a), repacked as GEMM2 A-frags.
        uint32_t ah2[8][4];
        #pragma unroll
        for (int j = 0; j < 16; ++j) {
            const int c = 8 * j + 2 * qt;
            const float2 bx = *reinterpret_cast<const float2*>(sb1a + c);
            const int ks2 = j >> 1;
            const int ix = (j & 1) * 2;
            ah2[ks2][ix + 0] = packh2(lrelu(acc[j][0] + bx.x), lrelu(acc[j][1] + bx.y));
            ah2[ks2][ix + 1] = packh2(lrelu(acc[j][2] + bx.x), lrelu(acc[j][3] + bx.y));
        }

        // --- GEMM 2 in two n-halves, scatter per half ---
        #pragma unroll
        for (int nh = 0; nh < 2; ++nh) {
            float a2[8][4];
            #pragma unroll
            for (int j = 0; j < 8; ++j)
                #pragma unroll
                for (int q = 0; q < 4; ++q) a2[j][q] = 0.f;

            #pragma unroll
            for (int ks = 0; ks < 8; ++ks) {
                #pragma unroll
                for (int np = 0; np < 4; ++np) {
                    uint32_t bh[4];
                    const uint32_t bb =
                        (uint32_t)(ks * 16 * PADK + nh * 64 + np * 16) * 2 + boff;
                    ldsm4t(bh, wbA + bb);
                    mma16816h(a2[2 * np + 0], ah2[ks], bh + 0);
                    mma16816h(a2[2 * np + 1], ah2[ks], bh + 2);
                }
            }

            // Scatter this half straight from accumulators
            #pragma unroll
            for (int nt = 0; nt < 8; ++nt) {
                const int c = nh * 64 + nt * 8 + 2 * qt;
                const float2 bx = *reinterpret_cast<const float2*>(sb1b + c);
                if (tgt0 >= 0)
                    red_add_v2(g_accum + (size_t)tgt0 * 128 + c,
                               a2[nt][0] + bx.x, a2[nt][1] + bx.y);
                if (tgt1 >= 0)
                    red_add_v2(g_accum + (size_t)tgt1 * 128 + c,
                               a2[nt][2] + bx.x, a2[nt][3] + bx.y);
            }
        }
    }
}

// ---------------------------------------------------------------------------
// Node MLP: warp-autonomous fp16 mma (NEW in R17 — same design as edge).
//
//   IN = [x_g (128) | a=g_accum (128) | u[batch] (64)]  (K=320, 20 k-steps)
//   H  = lrelu(IN @ W2a^T + b2a)      GEMM1: 320 HMMA/group
//   O  = H @ W2b^T + b2b              GEMM2: 128 HMMA/group
//   O written directly to out (coalesced float2 stores; no atomics).
// Node rows are consecutive -> A gather fully coalesced.
// SMEM: W2a^T fp16 [320][128+pad] (87KB) + W2b^T fp16 (35KB) + biases.
// ---------------------------------------------------------------------------
#define NTH2  512
#define N2_WA   0
#define N2_WA_BYTES (320 * PADK * 2)            // 87040
#define N2_WB   (N2_WA + N2_WA_BYTES)
#define N2_WB_BYTES (128 * PADK * 2)            // 34816
#define N2_B2A  (N2_WB + N2_WB_BYTES)           // float[128]
#define N2_B2B  (N2_B2A + 512)
#define N2_SMEM_BYTES (N2_B2B + 512)            // 122880

__global__ void __launch_bounds__(NTH2, 1)
node_kernel(const float* __restrict__ x_g,
            const float* __restrict__ u,
            const float* __restrict__ W2a, const float* __restrict__ b2a,
            const float* __restrict__ W2b, const float* __restrict__ b2b,
            const int* __restrict__ batch_g,
            float* __restrict__ out, int NG)
{
    extern __shared__ char smc[];
    const uint32_t sb = smem_to_u32(smc);
    uint16_t* Wa = reinterpret_cast<uint16_t*>(smc + N2_WA);
    uint16_t* Wb = reinterpret_cast<uint16_t*>(smc + N2_WB);
    float* sb2a = reinterpret_cast<float*>(smc + N2_B2A);
    float* sb2b = reinterpret_cast<float*>(smc + N2_B2B);

    const int tid  = threadIdx.x;
    const int wid  = tid >> 5;
    const int lane = tid & 31;

    // Stage W2a^T: Wa[k*PADK + n] = W2a[n*320 + k]   (n=out=128, k=in=320)
    for (int t = tid; t < 128 * 320; t += NTH2) {
        int n = t / 320, k = t % 320;
        Wa[k * PADK + n] = __half_as_ushort(__float2half_rn(W2a[t]));
    }
    // Stage W2b^T: Wb[k*PADK + n] = W2b[n*128 + k]
    for (int t = tid; t < 128 * 128; t += NTH2) {
        int n = t >> 7, k = t & 127;
        Wb[k * PADK + n] = __half_as_ushort(__float2half_rn(W2b[t]));
    }
    if (tid < 128) { sb2a[tid] = b2a[tid]; sb2b[tid] = b2b[tid]; }
    __syncthreads();

    const int qr = lane >> 2;
    const int qt = lane & 3;
    const uint32_t boff = ((uint32_t)(lane & 15) * PADK + (uint32_t)(lane >> 4) * 8) * 2;
    const uint32_t waA = sb + N2_WA, wbA = sb + N2_WB;

    const int nGroups = (NG + 15) >> 4;
    const int totalWarps = gridDim.x * (NTH2 / 32);

    for (int g = blockIdx.x * (NTH2 / 32) + wid; g < nGroups; g += totalWarps) {
        const int nbase = g * 16;

        // batch idx for this group's 16 nodes
        int my_b = 0;
        if (lane < 16) {
            int n = nbase + lane;
            if (n < NG) {
                int b = batch_g[n];
                if (b < 0) b = 0;
                if (b > 15) b = 15;
                my_b = b;
            }
        }
        const int b0 = __shfl_sync(0xFFFFFFFFu, my_b, qr);
        const int b1 = __shfl_sync(0xFFFFFFFFu, my_b, qr + 8);

        const int n0r = min(nbase + qr, NG - 1);
        const int n1r = min(nbase + qr + 8, NG - 1);
        const float* r0g = x_g + (size_t)n0r * 128;
        const float* r1g = x_g + (size_t)n1r * 128;
        const float* r0a = g_accum + (size_t)n0r * 128;
        const float* r1a = g_accum + (size_t)n1r * 128;
        const float* r0u = u + (size_t)b0 * 64;
        const float* r1u = u + (size_t)b1 * 64;

        // --- GEMM 1: K=320 (20 k-steps), acc over full n=128 ---
        float acc[16][4];
        #pragma unroll
        for (int j = 0; j < 16; ++j)
            #pragma unroll
            for (int q = 0; q < 4; ++q) acc[j][q] = 0.f;

        #pragma unroll
        for (int ks = 0; ks < 20; ++ks) {
            const int c0 = ks * 16 + 2 * qt;
            float2 v0, v1, v2, v3;
            if (ks < 8) {            // cols 0..127: x_g
                v0 = *reinterpret_cast<const float2*>(r0g + c0);
                v1 = *reinterpret_cast<const float2*>(r1g + c0);
                v2 = *reinterpret_cast<const float2*>(r0g + c0 + 8);
                v3 = *reinterpret_cast<const float2*>(r1g + c0 + 8);
            } else if (ks < 16) {    // cols 128..255: g_accum
                const int cc = c0 - 128;
                v0 = *reinterpret_cast<const float2*>(r0a + cc);
                v1 = *reinterpret_cast<const float2*>(r1a + cc);
                v2 = *reinterpret_cast<const float2*>(r0a + cc + 8);
                v3 = *reinterpret_cast<const float2*>(r1a + cc + 8);
            } else {                 // cols 256..319: u[batch]
                const int cc = c0 - 256;
                v0 = *reinterpret_cast<const float2*>(r0u + cc);
                v1 = *reinterpret_cast<const float2*>(r1u + cc);
                v2 = *reinterpret_cast<const float2*>(r0u + cc + 8);
                v3 = *reinterpret_cast<const float2*>(r1u + cc + 8);
            }
            uint32_t a[4];
            a[0] = packh2(v0.x, v0.y);
            a[1] = packh2(v1.x, v1.y);
            a[2] = packh2(v2.x, v2.y);
            a[3] = packh2(v3.x, v3.y);

            #pragma unroll
            for (int np = 0; np < 8; ++np) {
                uint32_t bh[4];
                const uint32_t bb = (uint32_t)(ks * 16 * PADK + np * 16) * 2 + boff;
                ldsm4t(bh, waA + bb);
                mma16816h(acc[2 * np + 0], a, bh + 0);
                mma16816h(acc[2 * np + 1], a, bh + 2);
            }
        }

        // Register epilogue: H = lrelu(acc + b2a) repacked as GEMM2 A-frags
        uint32_t ah2[8][4];
        #pragma unroll
        for (int j = 0; j < 16; ++j) {
            const int c = 8 * j + 2 * qt;
            const float2 bx = *reinterpret_cast<const float2*>(sb2a + c);
            const int ks2 = j >> 1;
            const int ix = (j & 1) * 2;
            ah2[ks2][ix + 0] = packh2(lrelu(acc[j][0] + bx.x), lrelu(acc[j][1] + bx.y));
            ah2[ks2][ix + 1] = packh2(lrelu(acc[j][2] + bx.x), lrelu(acc[j][3] + bx.y));
        }

        // --- GEMM 2: K=128, full n=128 ---
        #pragma unroll
        for (int j = 0; j < 16; ++j)
            #pragma unroll
            for (int q = 0; q < 4; ++q) acc[j][q] = 0.f;

        #pragma unroll
        for (int ks = 0; ks < 8; ++ks) {
            #pragma unroll
            for (int np = 0; np < 8; ++np) {
                uint32_t bh[4];
                const uint32_t bb = (uint32_t)(ks * 16 * PADK + np * 16) * 2 + boff;
                ldsm4t(bh, wbA + bb);
                mma16816h(acc[2 * np + 0], ah2[ks], bh + 0);
                mma16816h(acc[2 * np + 1], ah2[ks], bh + 2);
            }
        }

        // Store O = acc + b2b directly (coalesced float2)
        const int nr0 = nbase + qr;
        const int nr1 = nbase + qr + 8;
        #pragma unroll
        for (int j = 0; j < 16; ++j) {
            const int c = 8 * j + 2 * qt;
            const float2 bx = *reinterpret_cast<const float2*>(sb2b + c);
            if (nr0 < NG)
                *reinterpret_cast<float2*>(out + (size_t)nr0 * 128 + c) =
                    make_float2(acc[j][0] + bx.x, acc[j][1] + bx.y);
            if (nr1 < NG)
                *reinterpret_cast<float2*>(out + (size_t)nr1 * 128 + c) =
                    make_float2(acc[j][2] + bx.x, acc[j][3] + bx.y);
        }
    }
}

// ---------------------------------------------------------------------------
// kernel_launch
// Inputs: 0 x_h, 1 x_g, 2 edge_attr, 3 u, 4 W1a, 5 b1a, 6 W1b, 7 b1b,
//         8 W2a, 9 b2a, 10 W2b, 11 b2b, 12 edge_index (int32), 13 batch_g (int32)
// ---------------------------------------------------------------------------
extern "C" void kernel_launch(void* const* d_in, const int* in_sizes, int n_in,
                              void* d_out, int out_size) {
    const float* x_h       = (const float*)d_in[0];
    const float* x_g       = (const float*)d_in[1];
    const float* edge_attr = (const float*)d_in[2];
    const float* u         = (const float*)d_in[3];
    const float* W1a       = (const float*)d_in[4];
    const float* b1a       = (const float*)d_in[5];
    const float* W1b       = (const float*)d_in[6];
    const float* b1b       = (const float*)d_in[7];
    const float* W2a       = (const float*)d_in[8];
    const float* b2a       = (const float*)d_in[9];
    const float* W2b       = (const float*)d_in[10];
    const float* b2b       = (const float*)d_in[11];
    const int* eidx        = (const int*)d_in[12];
    const int* batch       = (const int*)d_in[13];
    float* out = (float*)d_out;

    const int E  = in_sizes[12] / 2;
    const int NG = in_sizes[1] / N_GC;

    cudaFuncSetAttribute(edge_kernel, cudaFuncAttributeMaxDynamicSharedMemorySize,
                         E_SMEM_BYTES);
    cudaFuncSetAttribute(node_kernel, cudaFuncAttributeMaxDynamicSharedMemorySize,
                         N2_SMEM_BYTES);

    zero_accum_kernel<<<1024, 256>>>();
    edge_kernel<<<152, ETH, E_SMEM_BYTES>>>(x_h, edge_attr, W1a, b1a, W1b, b1b,
                                            eidx, E);
    node_kernel<<<152, NTH2, N2_SMEM_BYTES>>>(x_g, u, W2a, b2a, W2b, b2b,
                                              batch, out, NG);
}